// round 13
// baseline (speedup 1.0000x reference)
#include <cuda_runtime.h>
#include <cuda_fp16.h>
#include <math.h>
#include <stdint.h>

#define BATCH 4
#define SEQ   4096
#define DIM   1024
#define NH    4
#define DH    256
#define FFD   4096
#define TOK   (BATCH*SEQ)   /* 16384 */
#define NBH   (BATCH*NH)    /* 16 */
#define KCH   16
#define CHUNK (SEQ/KCH)     /* 256 */

#define NPERS 296           /* persistent CTAs: 2/SM x 148 */

/* fp16 mma GEMM tiling: 128x128 CTA tile, 256 threads, 8 warps of 64x32 */
#define TM 128
#define TN 128
#define TK 64
#define APITCH 72
#define BPITCH 136
#define ABYTES (TM*APITCH*2)        /* 18432 */
#define BBYTES (TK*BPITCH*2)        /* 17408 */
#define STAGEB (ABYTES+BBYTES)      /* 35840 */
#define SMEM3  (3*STAGEB)           /* 107520: 2 CTAs/SM = 210KB < 228KB */

/* ctx mma tiling: 64x64 tiles, 128 threads, 4 warps of 32x32 */
#define CTK 64
#define CPITCH 72

// ---------------- scratch ---------------------------------------------------
__device__ float  g_x1  [(size_t)TOK*DIM];
__device__ float  g_part[NBH*KCH*2*DH];
__device__ __half g_h   [(size_t)TOK*DIM];
__device__ __half g_qh  [(size_t)TOK*DIM];      /* q token-major [b,n,h,dh] */
__device__ __half g_kh  [(size_t)NBH*SEQ*DH];
__device__ __half g_vh  [(size_t)NBH*SEQ*DH];
__device__ __half g_ctxh[(size_t)NBH*DH*DH];
__device__ __half g_w2h [(size_t)BATCH*DIM*DIM]; /* W2_b = blockdiag(ctx_{b,h}) @ wo */
__device__ __half g_ffh [(size_t)TOK*FFD];
__device__ __half g_x2h [(size_t)TOK*DIM];
__device__ __half g_wr  [(size_t)13*1024*1024];

/* offsets into g_wr (halves) */
#define OFF_QKV  (0)                 /* packed [1024][3072]: wq|wk|wv */
#define OFF_WO   (3*1024*1024)
#define OFF_WD   (4*1024*1024)
#define OFF_WFF1 (5*1024*1024)
#define OFF_WFF2 (9*1024*1024)

__device__ __forceinline__ float gelu_tanh(float x) {
    float x3 = x*x*x;
    return 0.5f*x*(1.0f + tanhf(0.7978845608028654f*(x + 0.044715f*x3)));
}
__device__ __forceinline__ uint32_t smem_u32(const void* p) {
    uint32_t a;
    asm("{ .reg .u64 t; cvta.to.shared.u64 t, %1; cvt.u32.u64 %0, t; }" : "=r"(a) : "l"(p));
    return a;
}
__device__ __forceinline__ void cp16(uint32_t dst, const void* src) {
    asm volatile("cp.async.cg.shared.global [%0], [%1], 16;" :: "r"(dst), "l"(src));
}
__device__ __forceinline__ void ldm_x4(uint32_t* r, uint32_t addr) {
    asm volatile("ldmatrix.sync.aligned.m8n8.x4.shared.b16 {%0,%1,%2,%3}, [%4];"
        : "=r"(r[0]), "=r"(r[1]), "=r"(r[2]), "=r"(r[3]) : "r"(addr));
}
__device__ __forceinline__ void ldm_x4_t(uint32_t* r, uint32_t addr) {
    asm volatile("ldmatrix.sync.aligned.m8n8.x4.trans.shared.b16 {%0,%1,%2,%3}, [%4];"
        : "=r"(r[0]), "=r"(r[1]), "=r"(r[2]), "=r"(r[3]) : "r"(addr));
}
__device__ __forceinline__ void mma_f16(float* c, uint32_t a0, uint32_t a1, uint32_t a2,
                                        uint32_t a3, uint32_t b0, uint32_t b1) {
    asm volatile("mma.sync.aligned.m16n8k16.row.col.f32.f16.f16.f32 "
        "{%0,%1,%2,%3}, {%4,%5,%6,%7}, {%8,%9}, {%0,%1,%2,%3};"
        : "+f"(c[0]), "+f"(c[1]), "+f"(c[2]), "+f"(c[3])
        : "r"(a0), "r"(a1), "r"(a2), "r"(a3), "r"(b0), "r"(b1));
}

// ---------------- fused weight fp32 -> fp16 conversion -----------------------
// segments (float4 units): qkv 3x262144 (strided pack), wo/wd 262144 each,
// wff1/wff2 1048576 each. total 3407872 float4.
#define D4 262144
#define F4 1048576
__global__ void cvt_all(const float* __restrict__ wq, const float* __restrict__ wk,
                        const float* __restrict__ wv, const float* __restrict__ wo,
                        const float* __restrict__ wd, const float* __restrict__ wff1,
                        const float* __restrict__ wff2, __half* __restrict__ wr)
{
    const int i = blockIdx.x * blockDim.x + threadIdx.x;
    const float* src;
    __half2* d2;
    if (i < 3*D4) {
        const int m = i / D4, j = i % D4;
        src = (m == 0) ? wq : (m == 1) ? wk : wv;
        const int row = j >> 8, c4 = j & 255;
        float4 v = ((const float4*)src)[j];
        d2 = (__half2*)(wr + OFF_QKV + (size_t)row*3072 + m*1024 + c4*4);
        d2[0] = __floats2half2_rn(v.x, v.y);
        d2[1] = __floats2half2_rn(v.z, v.w);
        return;
    }
    int j; size_t off;
    if      (i < 4*D4)        { j = i - 3*D4;        src = wo;   off = OFF_WO; }
    else if (i < 5*D4)        { j = i - 4*D4;        src = wd;   off = OFF_WD; }
    else if (i < 5*D4 + F4)   { j = i - 5*D4;        src = wff1; off = OFF_WFF1; }
    else                      { j = i - 5*D4 - F4;   src = wff2; off = OFF_WFF2; }
    float4 v = ((const float4*)src)[j];
    d2 = (__half2*)(wr + off + (size_t)j*4);
    d2[0] = __floats2half2_rn(v.x, v.y);
    d2[1] = __floats2half2_rn(v.z, v.w);
}

// ---------------- persistent fp16 mma GEMM, 128x128 tiles, 3-stage -----------
// MODE 0: C(fp32) = acc + bias
// MODE 2: C(fp16) = gelu(acc + bias)
// MODE 5: C(fp16) = acc + bias + res
// MODE 7: fused qkv: W=[1024][3072]; q -> Cv row-major [TOK][1024];
//         k -> bias cast scatter [b,h,n,dh]; v -> res cast scatter
// MODE 8: W2 batch tz=bh: A=ctx+tz*DH*DH, W=wo+(tz&3)*DH*Ncols,
//         C(fp16) at w2 + (tz>>2)*DIM*Ncols + (tz&3)*DH*Ncols
// MODE 9: batched over tz=b: A=qh+tz*SEQ*K, W=w2+tz*K*Ncols, res/C + tz*SEQ*Ncols
template<int MODE>
__global__ void __launch_bounds__(256, 2)
gemm_mma(const __half* __restrict__ A0, const __half* __restrict__ W0,
         const float* __restrict__ bias, const float* __restrict__ res0,
         void* __restrict__ Cv, int Ncols, int K, int gx, int gy, int gz)
{
    extern __shared__ char dsm[];
    uint32_t aAs[3], aBs[3];
    #pragma unroll
    for (int s = 0; s < 3; s++) {
        aAs[s] = smem_u32(dsm + s*STAGEB);
        aBs[s] = smem_u32(dsm + s*STAGEB + ABYTES);
    }

    const int tid  = threadIdx.x;
    const int lane = tid & 31;
    const int w    = tid >> 5;
    const int m0w  = (w >> 2) * 64;
    const int n0w  = (w & 3) * 32;
    const int NT   = K / TK;
    const int lr = lane >> 2;
    const int lc = lane & 3;
    const int l15 = lane & 15;
    const int lhi8 = (lane >> 4) * 8;

    const int ntiles = gx * gy * gz;
    for (int tile = blockIdx.x; tile < ntiles; tile += gridDim.x) {
        const int tx = tile % gx;
        const int t2 = tile / gx;
        const int ty = t2 % gy;
        const int tz = t2 / gy;
        const int row0 = ty * TM;
        const int col0 = tx * TN;

        const __half* A = A0;
        const __half* W = W0;
        const float*  res = res0;
        size_t cofs = 0;
        if (MODE == 8) {
            A += (size_t)tz * DH * DH;
            W += (size_t)(tz & 3) * DH * Ncols;
            cofs = (size_t)(tz >> 2) * DIM * Ncols + (size_t)(tz & 3) * DH * Ncols;
        }
        if (MODE == 9) {
            A += (size_t)tz * SEQ * K;
            W += (size_t)tz * K * Ncols;
            res += (size_t)tz * SEQ * Ncols;
            cofs = (size_t)tz * SEQ * Ncols;
        }

        auto fill = [&](int buf, int k0) {
            #pragma unroll
            for (int j = 0; j < 4; j++) {
                int f  = tid + 256*j;
                int r  = f >> 3, c8 = f & 7;
                cp16(aAs[buf] + (uint32_t)(r*APITCH + c8*8)*2,
                     A + (size_t)(row0 + r)*K + k0 + c8*8);
            }
            #pragma unroll
            for (int j = 0; j < 4; j++) {
                int f  = tid + 256*j;
                int kr = f >> 4, c8 = f & 15;
                cp16(aBs[buf] + (uint32_t)(kr*BPITCH + c8*8)*2,
                     W + (size_t)(k0 + kr)*Ncols + col0 + c8*8);
            }
            asm volatile("cp.async.commit_group;");
        };

        float acc[4][4][4];
        #pragma unroll
        for (int i = 0; i < 4; i++)
            #pragma unroll
            for (int j = 0; j < 4; j++)
                #pragma unroll
                for (int r = 0; r < 4; r++) acc[i][j][r] = 0.f;

        fill(0, 0);
        fill(1, TK);

        int buf = 0;
        for (int t = 0; t < NT; t++) {
            if (t + 1 < NT) asm volatile("cp.async.wait_group 1;");
            else            asm volatile("cp.async.wait_group 0;");
            __syncthreads();
            if (t + 2 < NT) fill((t + 2) % 3, (t + 2) * TK);

            const uint32_t a_lm = aAs[buf] + (uint32_t)((m0w + l15)*APITCH + lhi8)*2;
            const uint32_t b_lm = aBs[buf] + (uint32_t)(l15*BPITCH + n0w + lhi8)*2;

            #pragma unroll
            for (int kk = 0; kk < 4; kk++) {
                uint32_t af[4][4];
                #pragma unroll
                for (int mf = 0; mf < 4; mf++)
                    ldm_x4(af[mf], a_lm + (uint32_t)(mf*16*APITCH + kk*16)*2);

                uint32_t bf[2][4];
                #pragma unroll
                for (int np = 0; np < 2; np++)
                    ldm_x4_t(bf[np], b_lm + (uint32_t)(kk*16*BPITCH + np*16)*2);

                #pragma unroll
                for (int mf = 0; mf < 4; mf++)
                    #pragma unroll
                    for (int nf = 0; nf < 4; nf++)
                        mma_f16(acc[mf][nf],
                                af[mf][0], af[mf][1], af[mf][2], af[mf][3],
                                bf[nf >> 1][(nf & 1)*2], bf[nf >> 1][(nf & 1)*2 + 1]);
            }
            buf = (buf + 1 == 3) ? 0 : buf + 1;
        }

        // ---- epilogue ----
        float*  Cf = (float*)Cv;
        __half* Ch = (__half*)Cv;
        #pragma unroll
        for (int mf = 0; mf < 4; mf++) {
            #pragma unroll
            for (int half_ = 0; half_ < 2; half_++) {
                const int grow = row0 + m0w + mf*16 + lr + half_*8;
                #pragma unroll
                for (int nf = 0; nf < 4; nf++) {
                    const int gcol = col0 + n0w + nf*8 + 2*lc;
                    float v0 = acc[mf][nf][half_*2 + 0];
                    float v1 = acc[mf][nf][half_*2 + 1];
                    if (MODE == 7) {
                        const int mat  = gcol >> 10;
                        const int hcol = gcol & 1023;
                        if (mat == 0) {
                            *(__half2*)(Ch + (size_t)grow*DIM + hcol) = __floats2half2_rn(v0, v1);
                        } else {
                            const int head = hcol >> 8;
                            const int dh0  = hcol & 255;
                            const int b_   = grow >> 12;
                            const int n_   = grow & 4095;
                            const size_t off = ((size_t)((b_*NH + head)*SEQ + n_))*DH + dh0;
                            __half* dst = (mat == 1) ? (__half*)bias : (__half*)res;
                            *(__half2*)(dst + off) = __floats2half2_rn(v0, v1);
                        }
                    } else if (MODE == 8) {
                        *(__half2*)(Ch + cofs + (size_t)grow*Ncols + gcol) = __floats2half2_rn(v0, v1);
                    } else {
                        v0 += bias[gcol];
                        v1 += bias[gcol + 1];
                        if (MODE == 2) { v0 = gelu_tanh(v0); v1 = gelu_tanh(v1); }
                        if (MODE == 5 || MODE == 9) {
                            const float2 rv = *(const float2*)(res + (size_t)grow*Ncols + gcol);
                            v0 += rv.x; v1 += rv.y;
                        }
                        if (MODE == 2 || MODE == 5) {
                            *(__half2*)(Ch + (size_t)grow*Ncols + gcol) = __floats2half2_rn(v0, v1);
                        } else {
                            *(float2*)(Cf + cofs + (size_t)grow*Ncols + gcol) = make_float2(v0, v1);
                        }
                    }
                }
            }
        }
        __syncthreads();   /* guard next tile's smem refill vs lagging readers */
    }
}

// ---------------- ctx = k^T @ v (fp16 mma, both operands transposed) --------
__global__ void __launch_bounds__(128, 2)
ctx_mma(const __half* __restrict__ kh, const __half* __restrict__ vh,
        __half* __restrict__ ctx)
{
    __shared__ __half Ks[2][CTK][CPITCH];
    __shared__ __half Vs[2][CTK][CPITCH];
    const int bh = blockIdx.z;
    const int d0 = blockIdx.y * 64, e0 = blockIdx.x * 64;
    const __half* kb = kh + (size_t)bh*SEQ*DH;
    const __half* vb = vh + (size_t)bh*SEQ*DH;
    const int tid = threadIdx.x, lane = tid & 31, w = tid >> 5;
    const int m0w = (w >> 1) * 32, n0w = (w & 1) * 32;

    const uint32_t kbase[2] = { smem_u32(&Ks[0][0][0]), smem_u32(&Ks[1][0][0]) };
    const uint32_t vbase[2] = { smem_u32(&Vs[0][0][0]), smem_u32(&Vs[1][0][0]) };

    auto fill = [&](int buf, int n0) {
        #pragma unroll
        for (int j = 0; j < 4; j++) {
            int f = tid + 128*j;
            int r = f >> 3, c8 = f & 7;
            cp16(kbase[buf] + (uint32_t)(r*CPITCH + c8*8)*2, kb + (size_t)(n0+r)*DH + d0 + c8*8);
            cp16(vbase[buf] + (uint32_t)(r*CPITCH + c8*8)*2, vb + (size_t)(n0+r)*DH + e0 + c8*8);
        }
        asm volatile("cp.async.commit_group;");
    };

    float acc[2][4][4];
    #pragma unroll
    for (int i = 0; i < 2; i++)
        #pragma unroll
        for (int j = 0; j < 4; j++)
            #pragma unroll
            for (int r = 0; r < 4; r++) acc[i][j][r] = 0.f;

    const int arow = (lane & 7) + ((lane >> 4) << 3);
    const int acol = ((lane >> 3) & 1) * 8;
    const int l15 = lane & 15, lhi8 = (lane >> 4) * 8;
    const int lr = lane >> 2, lc = lane & 3;

    fill(0, 0);
    const int NTc = SEQ / CTK;
    for (int t = 0; t < NTc; t++) {
        if (t + 1 < NTc) {
            fill((t + 1) & 1, (t + 1) * CTK);
            asm volatile("cp.async.wait_group 1;");
        } else {
            asm volatile("cp.async.wait_group 0;");
        }
        __syncthreads();
        const uint32_t ka = kbase[t & 1];
        const uint32_t va = vbase[t & 1];

        #pragma unroll
        for (int kk = 0; kk < 4; kk++) {
            uint32_t af[2][4];
            #pragma unroll
            for (int mf = 0; mf < 2; mf++)
                ldm_x4_t(af[mf], ka + (uint32_t)((kk*16 + arow)*CPITCH + m0w + mf*16 + acol)*2);
            uint32_t bf[2][4];
            #pragma unroll
            for (int np = 0; np < 2; np++)
                ldm_x4_t(bf[np], va + (uint32_t)((kk*16 + l15)*CPITCH + n0w + np*16 + lhi8)*2);
            #pragma unroll
            for (int mf = 0; mf < 2; mf++)
                #pragma unroll
                for (int nf = 0; nf < 4; nf++)
                    mma_f16(acc[mf][nf],
                            af[mf][0], af[mf][1], af[mf][2], af[mf][3],
                            bf[nf >> 1][(nf & 1)*2], bf[nf >> 1][(nf & 1)*2 + 1]);
        }
        __syncthreads();
    }

    __half* cb = ctx + (size_t)bh*DH*DH;
    #pragma unroll
    for (int mf = 0; mf < 2; mf++)
        #pragma unroll
        for (int half_ = 0; half_ < 2; half_++) {
            const int grow = d0 + m0w + mf*16 + lr + half_*8;
            #pragma unroll
            for (int nf = 0; nf < 4; nf++) {
                const int gcol = e0 + n0w + nf*8 + 2*lc;
                *(__half2*)(cb + (size_t)grow*DH + gcol) =
                    __floats2half2_rn(acc[mf][nf][half_*2], acc[mf][nf][half_*2 + 1]);
            }
        }
}

// ---------------- LayerNorm (fp32 in, fp16 out) ------------------------------
__global__ void ln_kernel(const float* __restrict__ x, const float* __restrict__ g,
                          const float* __restrict__ b, __half* __restrict__ out)
{
    __shared__ float red[16];
    __shared__ float s_mu, s_rstd;
    const int row = blockIdx.x, t = threadIdx.x;
    const float4 v = ((const float4*)(x + (size_t)row*DIM))[t];
    float s  = v.x + v.y + v.z + v.w;
    float ss = fmaf(v.x,v.x, fmaf(v.y,v.y, fmaf(v.z,v.z, v.w*v.w)));
    #pragma unroll
    for (int o = 16; o > 0; o >>= 1) {
        s  += __shfl_xor_sync(0xffffffffu, s,  o);
        ss += __shfl_xor_sync(0xffffffffu, ss, o);
    }
    const int w = t >> 5, lane = t & 31;
    if (lane == 0) { red[w] = s; red[8+w] = ss; }
    __syncthreads();
    if (t == 0) {
        float S = 0.f, SS = 0.f;
        #pragma unroll
        for (int i = 0; i < 8; i++) { S += red[i]; SS += red[8+i]; }
        float mu  = S  * (1.0f/DIM);
        float var = SS * (1.0f/DIM) - mu*mu;
        s_mu = mu; s_rstd = rsqrtf(var + 1e-5f);
    }
    __syncthreads();
    const float mu = s_mu, r = s_rstd;
    const float4 gv = ((const float4*)g)[t];
    const float4 bv = ((const float4*)b)[t];
    __half2* o2 = (__half2*)(out + (size_t)row*DIM);
    o2[t*2]   = __floats2half2_rn((v.x-mu)*r*gv.x + bv.x, (v.y-mu)*r*gv.y + bv.y);
    o2[t*2+1] = __floats2half2_rn((v.z-mu)*r*gv.z + bv.z, (v.w-mu)*r*gv.w + bv.w);
}

// ---------------- q softmax over head dim (fp16 in-place) -------------------
__global__ void qsm_kernel(__half* __restrict__ q)
{
    const int warp = (blockIdx.x * blockDim.x + threadIdx.x) >> 5;
    const int lane = threadIdx.x & 31;
    __half* row = q + (size_t)warp * DH;
    float v[8];
    float m = -INFINITY;
    #pragma unroll
    for (int j = 0; j < 8; j++) {
        v[j] = __half2float(row[j*32 + lane]) * 0.25f;
        m = fmaxf(m, v[j]);
    }
    #pragma unroll
    for (int o = 16; o > 0; o >>= 1) m = fmaxf(m, __shfl_xor_sync(0xffffffffu, m, o));
    float s = 0.f;
    #pragma unroll
    for (int j = 0; j < 8; j++) { v[j] = expf(v[j] - m); s += v[j]; }
    #pragma unroll
    for (int o = 16; o > 0; o >>= 1) s += __shfl_xor_sync(0xffffffffu, s, o);
    const float inv = 1.0f / s;
    #pragma unroll
    for (int j = 0; j < 8; j++) row[j*32 + lane] = __float2half_rn(v[j] * inv);
}

// ---------------- k softmax over sequence dim (2-pass, fp16 in-place) -------
__global__ void ksm_partial(const __half* __restrict__ k, float* __restrict__ part)
{
    const int bh = blockIdx.y, ch = blockIdx.x, t = threadIdx.x;
    const __half* kp = k + ((size_t)bh*SEQ + (size_t)ch*CHUNK)*DH + t;
    float m = -INFINITY, s = 0.f;
    for (int i = 0; i < CHUNK; i++) {
        const float vv = __half2float(kp[(size_t)i*DH]) * 0.25f;
        const float nm = fmaxf(m, vv);
        s = s*expf(m - nm) + expf(vv - nm);
        m = nm;
    }
    float* pp = part + (size_t)((bh*KCH + ch)*2)*DH;
    pp[t] = m; pp[DH + t] = s;
}

__global__ void ksm_norm(__half* __restrict__ k, const float* __restrict__ part)
{
    const int bh = blockIdx.y, ch = blockIdx.x, t = threadIdx.x;
    float M = -INFINITY;
    #pragma unroll
    for (int c = 0; c < KCH; c++)
        M = fmaxf(M, part[(size_t)((bh*KCH + c)*2)*DH + t]);
    float S = 0.f;
    #pragma unroll
    for (int c = 0; c < KCH; c++) {
        const float* pp = part + (size_t)((bh*KCH + c)*2)*DH;
        S += pp[DH + t] * expf(pp[t] - M);
    }
    const float inv = 1.0f / S;
    __half* kp = k + ((size_t)bh*SEQ + (size_t)ch*CHUNK)*DH + t;
    for (int i = 0; i < CHUNK; i++) {
        const float vv = __half2float(kp[(size_t)i*DH]) * 0.25f;
        kp[(size_t)i*DH] = __float2half_rn(expf(vv - M) * inv);
    }
}

// ---------------- launch ----------------------------------------------------
extern "C" void kernel_launch(void* const* d_in, const int* in_sizes, int n_in,
                              void* d_out, int out_size)
{
    const float* x    = (const float*)d_in[0];
    const float* ln1g = (const float*)d_in[1];
    const float* ln1b = (const float*)d_in[2];
    const float* wq   = (const float*)d_in[3];
    const float* wk   = (const float*)d_in[4];
    const float* wv   = (const float*)d_in[5];
    const float* wo   = (const float*)d_in[6];
    const float* bo   = (const float*)d_in[7];
    const float* ln2g = (const float*)d_in[8];
    const float* ln2b = (const float*)d_in[9];
    const float* wff1 = (const float*)d_in[10];
    const float* bff1 = (const float*)d_in[11];
    const float* wff2 = (const float*)d_in[12];
    const float* bff2 = (const float*)d_in[13];
    const float* wd   = (const float*)d_in[14];
    const float* bd   = (const float*)d_in[15];
    float* out = (float*)d_out;

    float *x1,*part;
    __half *h,*qh,*kh,*vh,*ctxh,*w2h,*ffh,*x2h,*wr;
    cudaGetSymbolAddress((void**)&x1,   g_x1);
    cudaGetSymbolAddress((void**)&part, g_part);
    cudaGetSymbolAddress((void**)&h,    g_h);
    cudaGetSymbolAddress((void**)&qh,   g_qh);
    cudaGetSymbolAddress((void**)&kh,   g_kh);
    cudaGetSymbolAddress((void**)&vh,   g_vh);
    cudaGetSymbolAddress((void**)&ctxh, g_ctxh);
    cudaGetSymbolAddress((void**)&w2h,  g_w2h);
    cudaGetSymbolAddress((void**)&ffh,  g_ffh);
    cudaGetSymbolAddress((void**)&x2h,  g_x2h);
    cudaGetSymbolAddress((void**)&wr,   g_wr);

    cudaFuncSetAttribute(gemm_mma<0>, cudaFuncAttributeMaxDynamicSharedMemorySize, SMEM3);
    cudaFuncSetAttribute(gemm_mma<2>, cudaFuncAttributeMaxDynamicSharedMemorySize, SMEM3);
    cudaFuncSetAttribute(gemm_mma<5>, cudaFuncAttributeMaxDynamicSharedMemorySize, SMEM3);
    cudaFuncSetAttribute(gemm_mma<7>, cudaFuncAttributeMaxDynamicSharedMemorySize, SMEM3);
    cudaFuncSetAttribute(gemm_mma<8>, cudaFuncAttributeMaxDynamicSharedMemorySize, SMEM3);
    cudaFuncSetAttribute(gemm_mma<9>, cudaFuncAttributeMaxDynamicSharedMemorySize, SMEM3);

    // --- convert all weights to fp16 in one launch ---
    cvt_all<<<(5*D4 + 2*F4)/256, 256>>>(wq, wk, wv, wo, wd, wff1, wff2, wr);

    // --- attention block ---
    ln_kernel<<<TOK, 256>>>(x, ln1g, ln1b, h);
    gemm_mma<7><<<NPERS, 256, SMEM3>>>(h, wr + OFF_QKV,
                                       (const float*)kh, (const float*)vh,
                                       qh, 3*DIM, DIM, 24, 128, 1);
    qsm_kernel<<<8192, 256>>>(qh);
    ksm_partial<<<dim3(KCH, NBH), 256>>>(kh, part);
    ksm_norm   <<<dim3(KCH, NBH), 256>>>(kh, part);
    ctx_mma    <<<dim3(4, 4, NBH), 128>>>(kh, vh, ctxh);
    gemm_mma<8><<<NPERS, 256, SMEM3>>>(ctxh, wr + OFF_WO, nullptr, nullptr,
                                       w2h, DIM, DH, 8, 2, NBH);
    gemm_mma<9><<<NPERS, 256, SMEM3>>>(qh, w2h, bo, x, x1, DIM, DIM, 8, 32, BATCH);

    // --- FFN block ---
    ln_kernel<<<TOK, 256>>>(x1, ln2g, ln2b, h);
    gemm_mma<2><<<NPERS, 256, SMEM3>>>(h, wr + OFF_WFF1, bff1, nullptr, ffh, FFD, DIM,
                                       32, 128, 1);
    gemm_mma<5><<<NPERS, 256, SMEM3>>>(ffh, wr + OFF_WFF2, bff2, x1, x2h, DIM, FFD,
                                       8, 128, 1);

    // --- trailing dense ---
    gemm_mma<0><<<NPERS, 256, SMEM3>>>(x2h, wr + OFF_WD, bd, nullptr, out, DIM, DIM,
                                       8, 128, 1);
}

// round 14
// speedup vs baseline: 1.0113x; 1.0113x over previous
#include <cuda_runtime.h>
#include <cuda_fp16.h>
#include <math.h>
#include <stdint.h>

#define BATCH 4
#define SEQ   4096
#define DIM   1024
#define NH    4
#define DH    256
#define FFD   4096
#define TOK   (BATCH*SEQ)   /* 16384 */
#define NBH   (BATCH*NH)    /* 16 */
#define KCH   16
#define CHUNK (SEQ/KCH)     /* 256 */

/* fp16 mma GEMM tiling: 128x128 CTA tile, 256 threads, 8 warps of 64x32 */
#define TM 128
#define TN 128
#define TK 64
#define APITCH 72
#define BPITCH 136
#define ABYTES (TM*APITCH*2)        /* 18432 */
#define BBYTES (TK*BPITCH*2)        /* 17408 */
#define STAGEB (ABYTES+BBYTES)      /* 35840 */
#define SMEM3  (3*STAGEB)           /* 107520: 2 CTAs/SM = 210KB < 228KB */

/* ctx mma tiling: 64x64 tiles, 128 threads, 4 warps of 32x32 */
#define CTK 64
#define CPITCH 72

// ---------------- scratch ---------------------------------------------------
__device__ float  g_x1  [(size_t)TOK*DIM];
__device__ float  g_part[NBH*KCH*2*DH];
__device__ __half g_h   [(size_t)TOK*DIM];
__device__ __half g_qh  [(size_t)TOK*DIM];      /* q token-major [b,n,h,dh] */
__device__ __half g_kh  [(size_t)NBH*SEQ*DH];
__device__ __half g_vh  [(size_t)NBH*SEQ*DH];
__device__ __half g_ctxh[(size_t)NBH*DH*DH];
__device__ __half g_w2h [(size_t)BATCH*DIM*DIM]; /* W2_b = blockdiag(ctx_{b,h}) @ wo */
__device__ __half g_ffh [(size_t)TOK*FFD];
__device__ __half g_x2h [(size_t)TOK*DIM];
__device__ __half g_wr  [(size_t)13*1024*1024];

/* offsets into g_wr (halves) */
#define OFF_QKV  (0)                 /* packed [1024][3072]: wq|wk|wv */
#define OFF_WO   (3*1024*1024)
#define OFF_WD   (4*1024*1024)
#define OFF_WFF1 (5*1024*1024)
#define OFF_WFF2 (9*1024*1024)

__device__ __forceinline__ float gelu_tanh(float x) {
    float x3 = x*x*x;
    return 0.5f*x*(1.0f + tanhf(0.7978845608028654f*(x + 0.044715f*x3)));
}
__device__ __forceinline__ uint32_t smem_u32(const void* p) {
    uint32_t a;
    asm("{ .reg .u64 t; cvta.to.shared.u64 t, %1; cvt.u32.u64 %0, t; }" : "=r"(a) : "l"(p));
    return a;
}
__device__ __forceinline__ void cp16(uint32_t dst, const void* src) {
    asm volatile("cp.async.cg.shared.global [%0], [%1], 16;" :: "r"(dst), "l"(src));
}
__device__ __forceinline__ void ldm_x4(uint32_t* r, uint32_t addr) {
    asm volatile("ldmatrix.sync.aligned.m8n8.x4.shared.b16 {%0,%1,%2,%3}, [%4];"
        : "=r"(r[0]), "=r"(r[1]), "=r"(r[2]), "=r"(r[3]) : "r"(addr));
}
__device__ __forceinline__ void ldm_x4_t(uint32_t* r, uint32_t addr) {
    asm volatile("ldmatrix.sync.aligned.m8n8.x4.trans.shared.b16 {%0,%1,%2,%3}, [%4];"
        : "=r"(r[0]), "=r"(r[1]), "=r"(r[2]), "=r"(r[3]) : "r"(addr));
}
__device__ __forceinline__ void mma_f16(float* c, uint32_t a0, uint32_t a1, uint32_t a2,
                                        uint32_t a3, uint32_t b0, uint32_t b1) {
    asm volatile("mma.sync.aligned.m16n8k16.row.col.f32.f16.f16.f32 "
        "{%0,%1,%2,%3}, {%4,%5,%6,%7}, {%8,%9}, {%0,%1,%2,%3};"
        : "+f"(c[0]), "+f"(c[1]), "+f"(c[2]), "+f"(c[3])
        : "r"(a0), "r"(a1), "r"(a2), "r"(a3), "r"(b0), "r"(b1));
}

// ---------------- fused ln1 + weight conversion ------------------------------
// blocks [0, TOK):              LayerNorm row = blockIdx.x  (x -> h fp16)
// blocks [TOK, TOK+13312):      weight cvt, i = (blockIdx.x-TOK)*256 + tid
#define D4 262144
#define F4 1048576
#define NCVT ((5*D4 + 2*F4)/256)     /* 13312 */
__global__ void ln1_cvt(const float* __restrict__ x, const float* __restrict__ g,
                        const float* __restrict__ b, __half* __restrict__ out,
                        const float* __restrict__ wq, const float* __restrict__ wk,
                        const float* __restrict__ wv, const float* __restrict__ wo,
                        const float* __restrict__ wd, const float* __restrict__ wff1,
                        const float* __restrict__ wff2, __half* __restrict__ wr)
{
    const int t = threadIdx.x;
    if (blockIdx.x >= TOK) {
        const int i = (blockIdx.x - TOK) * 256 + t;
        const float* src;
        __half2* d2;
        if (i < 3*D4) {
            const int m = i / D4, j = i % D4;
            src = (m == 0) ? wq : (m == 1) ? wk : wv;
            const int row = j >> 8, c4 = j & 255;
            float4 v = ((const float4*)src)[j];
            d2 = (__half2*)(wr + OFF_QKV + (size_t)row*3072 + m*1024 + c4*4);
            d2[0] = __floats2half2_rn(v.x, v.y);
            d2[1] = __floats2half2_rn(v.z, v.w);
            return;
        }
        int j; size_t off;
        if      (i < 4*D4)      { j = i - 3*D4;      src = wo;   off = OFF_WO; }
        else if (i < 5*D4)      { j = i - 4*D4;      src = wd;   off = OFF_WD; }
        else if (i < 5*D4 + F4) { j = i - 5*D4;      src = wff1; off = OFF_WFF1; }
        else                    { j = i - 5*D4 - F4; src = wff2; off = OFF_WFF2; }
        float4 v = ((const float4*)src)[j];
        d2 = (__half2*)(wr + off + (size_t)j*4);
        d2[0] = __floats2half2_rn(v.x, v.y);
        d2[1] = __floats2half2_rn(v.z, v.w);
        return;
    }
    __shared__ float red[16];
    __shared__ float s_mu, s_rstd;
    const int row = blockIdx.x;
    const float4 v = ((const float4*)(x + (size_t)row*DIM))[t];
    float s  = v.x + v.y + v.z + v.w;
    float ss = fmaf(v.x,v.x, fmaf(v.y,v.y, fmaf(v.z,v.z, v.w*v.w)));
    #pragma unroll
    for (int o = 16; o > 0; o >>= 1) {
        s  += __shfl_xor_sync(0xffffffffu, s,  o);
        ss += __shfl_xor_sync(0xffffffffu, ss, o);
    }
    const int w = t >> 5, lane = t & 31;
    if (lane == 0) { red[w] = s; red[8+w] = ss; }
    __syncthreads();
    if (t == 0) {
        float S = 0.f, SS = 0.f;
        #pragma unroll
        for (int i = 0; i < 8; i++) { S += red[i]; SS += red[8+i]; }
        float mu  = S  * (1.0f/DIM);
        float var = SS * (1.0f/DIM) - mu*mu;
        s_mu = mu; s_rstd = rsqrtf(var + 1e-5f);
    }
    __syncthreads();
    const float mu = s_mu, r = s_rstd;
    const float4 gv = ((const float4*)g)[t];
    const float4 bv = ((const float4*)b)[t];
    __half2* o2 = (__half2*)(out + (size_t)row*DIM);
    o2[t*2]   = __floats2half2_rn((v.x-mu)*r*gv.x + bv.x, (v.y-mu)*r*gv.y + bv.y);
    o2[t*2+1] = __floats2half2_rn((v.z-mu)*r*gv.z + bv.z, (v.w-mu)*r*gv.w + bv.w);
}

// ---------------- fp16 mma GEMM, 128x128 tiles, 3-stage, 1 bar/iter ----------
// MODE 0: C(fp32) = acc + bias
// MODE 2: C(fp16) = gelu(acc + bias)
// MODE 5: C(fp16) = acc + bias + res
// MODE 7: fused qkv: W=[1024][3072]; q -> Cv row-major [TOK][1024];
//         k -> bias cast scatter [b,h,n,dh]; v -> res cast scatter
// MODE 8: W2 batch z=bh: A=ctx+z*DH*DH, W=wo+(z&3)*DH*Ncols,
//         C(fp16) at w2 + (z>>2)*DIM*Ncols + (z&3)*DH*Ncols
// MODE 9: batched over z=b: A=qh+z*SEQ*K, W=w2+z*K*Ncols, res/C + z*SEQ*Ncols
template<int MODE>
__global__ void __launch_bounds__(256, 2)
gemm_mma(const __half* __restrict__ A, const __half* __restrict__ W,
         const float* __restrict__ bias, const float* __restrict__ res,
         void* __restrict__ Cv, int Ncols, int K)
{
    extern __shared__ char dsm[];
    uint32_t aAs[3], aBs[3];
    #pragma unroll
    for (int s = 0; s < 3; s++) {
        aAs[s] = smem_u32(dsm + s*STAGEB);
        aBs[s] = smem_u32(dsm + s*STAGEB + ABYTES);
    }

    size_t cofs = 0;
    if (MODE == 8) {
        const int z = blockIdx.z;
        A += (size_t)z * DH * DH;
        W += (size_t)(z & 3) * DH * Ncols;
        cofs = (size_t)(z >> 2) * DIM * Ncols + (size_t)(z & 3) * DH * Ncols;
    }
    if (MODE == 9) {
        const int z = blockIdx.z;
        A += (size_t)z * SEQ * K;
        W += (size_t)z * K * Ncols;
        res += (size_t)z * SEQ * Ncols;
        cofs = (size_t)z * SEQ * Ncols;
    }

    const int tid  = threadIdx.x;
    const int lane = tid & 31;
    const int w    = tid >> 5;
    const int m0w  = (w >> 2) * 64;
    const int n0w  = (w & 3) * 32;
    const int row0 = blockIdx.y * TM;
    const int col0 = blockIdx.x * TN;
    const int NT   = K / TK;

    const int lr = lane >> 2;
    const int lc = lane & 3;
    const int l15 = lane & 15;
    const int lhi8 = (lane >> 4) * 8;

    auto fill = [&](int buf, int k0) {
        #pragma unroll
        for (int j = 0; j < 4; j++) {
            int f  = tid + 256*j;
            int r  = f >> 3, c8 = f & 7;
            cp16(aAs[buf] + (uint32_t)(r*APITCH + c8*8)*2,
                 A + (size_t)(row0 + r)*K + k0 + c8*8);
        }
        #pragma unroll
        for (int j = 0; j < 4; j++) {
            int f  = tid + 256*j;
            int kr = f >> 4, c8 = f & 15;
            cp16(aBs[buf] + (uint32_t)(kr*BPITCH + c8*8)*2,
                 W + (size_t)(k0 + kr)*Ncols + col0 + c8*8);
        }
        asm volatile("cp.async.commit_group;");
    };

    float acc[4][4][4];
    #pragma unroll
    for (int i = 0; i < 4; i++)
        #pragma unroll
        for (int j = 0; j < 4; j++)
            #pragma unroll
            for (int r = 0; r < 4; r++) acc[i][j][r] = 0.f;

    fill(0, 0);
    fill(1, TK);

    int buf = 0;
    for (int t = 0; t < NT; t++) {
        if (t + 1 < NT) asm volatile("cp.async.wait_group 1;");
        else            asm volatile("cp.async.wait_group 0;");
        __syncthreads();
        if (t + 2 < NT) fill((t + 2) % 3, (t + 2) * TK);

        const uint32_t a_lm = aAs[buf] + (uint32_t)((m0w + l15)*APITCH + lhi8)*2;
        const uint32_t b_lm = aBs[buf] + (uint32_t)(l15*BPITCH + n0w + lhi8)*2;

        #pragma unroll
        for (int kk = 0; kk < 4; kk++) {
            uint32_t af[4][4];
            #pragma unroll
            for (int mf = 0; mf < 4; mf++)
                ldm_x4(af[mf], a_lm + (uint32_t)(mf*16*APITCH + kk*16)*2);

            uint32_t bf[2][4];
            #pragma unroll
            for (int np = 0; np < 2; np++)
                ldm_x4_t(bf[np], b_lm + (uint32_t)(kk*16*BPITCH + np*16)*2);

            #pragma unroll
            for (int mf = 0; mf < 4; mf++)
                #pragma unroll
                for (int nf = 0; nf < 4; nf++)
                    mma_f16(acc[mf][nf],
                            af[mf][0], af[mf][1], af[mf][2], af[mf][3],
                            bf[nf >> 1][(nf & 1)*2], bf[nf >> 1][(nf & 1)*2 + 1]);
        }
        buf = (buf + 1 == 3) ? 0 : buf + 1;
    }

    // ---- epilogue ----
    float*  Cf = (float*)Cv;
    __half* Ch = (__half*)Cv;
    #pragma unroll
    for (int mf = 0; mf < 4; mf++) {
        #pragma unroll
        for (int half_ = 0; half_ < 2; half_++) {
            const int grow = row0 + m0w + mf*16 + lr + half_*8;
            #pragma unroll
            for (int nf = 0; nf < 4; nf++) {
                const int gcol = col0 + n0w + nf*8 + 2*lc;
                float v0 = acc[mf][nf][half_*2 + 0];
                float v1 = acc[mf][nf][half_*2 + 1];
                if (MODE == 7) {
                    const int mat  = gcol >> 10;
                    const int hcol = gcol & 1023;
                    if (mat == 0) {
                        *(__half2*)(Ch + (size_t)grow*DIM + hcol) = __floats2half2_rn(v0, v1);
                    } else {
                        const int head = hcol >> 8;
                        const int dh0  = hcol & 255;
                        const int b_   = grow >> 12;
                        const int n_   = grow & 4095;
                        const size_t off = ((size_t)((b_*NH + head)*SEQ + n_))*DH + dh0;
                        __half* dst = (mat == 1) ? (__half*)bias : (__half*)res;
                        *(__half2*)(dst + off) = __floats2half2_rn(v0, v1);
                    }
                } else if (MODE == 8) {
                    *(__half2*)(Ch + cofs + (size_t)grow*Ncols + gcol) = __floats2half2_rn(v0, v1);
                } else {
                    v0 += bias[gcol];
                    v1 += bias[gcol + 1];
                    if (MODE == 2) { v0 = gelu_tanh(v0); v1 = gelu_tanh(v1); }
                    if (MODE == 5 || MODE == 9) {
                        const float2 rv = *(const float2*)(res + (size_t)grow*Ncols + gcol);
                        v0 += rv.x; v1 += rv.y;
                    }
                    if (MODE == 2 || MODE == 5) {
                        *(__half2*)(Ch + (size_t)grow*Ncols + gcol) = __floats2half2_rn(v0, v1);
                    } else {
                        *(float2*)(Cf + cofs + (size_t)grow*Ncols + gcol) = make_float2(v0, v1);
                    }
                }
            }
        }
    }
}

// ---------------- ctx = k^T @ v (fp16 mma, both operands transposed) --------
__global__ void __launch_bounds__(128, 2)
ctx_mma(const __half* __restrict__ kh, const __half* __restrict__ vh,
        __half* __restrict__ ctx)
{
    __shared__ __half Ks[2][CTK][CPITCH];
    __shared__ __half Vs[2][CTK][CPITCH];
    const int bh = blockIdx.z;
    const int d0 = blockIdx.y * 64, e0 = blockIdx.x * 64;
    const __half* kb = kh + (size_t)bh*SEQ*DH;
    const __half* vb = vh + (size_t)bh*SEQ*DH;
    const int tid = threadIdx.x, lane = tid & 31, w = tid >> 5;
    const int m0w = (w >> 1) * 32, n0w = (w & 1) * 32;

    const uint32_t kbase[2] = { smem_u32(&Ks[0][0][0]), smem_u32(&Ks[1][0][0]) };
    const uint32_t vbase[2] = { smem_u32(&Vs[0][0][0]), smem_u32(&Vs[1][0][0]) };

    auto fill = [&](int buf, int n0) {
        #pragma unroll
        for (int j = 0; j < 4; j++) {
            int f = tid + 128*j;
            int r = f >> 3, c8 = f & 7;
            cp16(kbase[buf] + (uint32_t)(r*CPITCH + c8*8)*2, kb + (size_t)(n0+r)*DH + d0 + c8*8);
            cp16(vbase[buf] + (uint32_t)(r*CPITCH + c8*8)*2, vb + (size_t)(n0+r)*DH + e0 + c8*8);
        }
        asm volatile("cp.async.commit_group;");
    };

    float acc[2][4][4];
    #pragma unroll
    for (int i = 0; i < 2; i++)
        #pragma unroll
        for (int j = 0; j < 4; j++)
            #pragma unroll
            for (int r = 0; r < 4; r++) acc[i][j][r] = 0.f;

    const int arow = (lane & 7) + ((lane >> 4) << 3);
    const int acol = ((lane >> 3) & 1) * 8;
    const int l15 = lane & 15, lhi8 = (lane >> 4) * 8;
    const int lr = lane >> 2, lc = lane & 3;

    fill(0, 0);
    const int NTc = SEQ / CTK;
    for (int t = 0; t < NTc; t++) {
        if (t + 1 < NTc) {
            fill((t + 1) & 1, (t + 1) * CTK);
            asm volatile("cp.async.wait_group 1;");
        } else {
            asm volatile("cp.async.wait_group 0;");
        }
        __syncthreads();
        const uint32_t ka = kbase[t & 1];
        const uint32_t va = vbase[t & 1];

        #pragma unroll
        for (int kk = 0; kk < 4; kk++) {
            uint32_t af[2][4];
            #pragma unroll
            for (int mf = 0; mf < 2; mf++)
                ldm_x4_t(af[mf], ka + (uint32_t)((kk*16 + arow)*CPITCH + m0w + mf*16 + acol)*2);
            uint32_t bf[2][4];
            #pragma unroll
            for (int np = 0; np < 2; np++)
                ldm_x4_t(bf[np], va + (uint32_t)((kk*16 + l15)*CPITCH + n0w + np*16 + lhi8)*2);
            #pragma unroll
            for (int mf = 0; mf < 2; mf++)
                #pragma unroll
                for (int nf = 0; nf < 4; nf++)
                    mma_f16(acc[mf][nf],
                            af[mf][0], af[mf][1], af[mf][2], af[mf][3],
                            bf[nf >> 1][(nf & 1)*2], bf[nf >> 1][(nf & 1)*2 + 1]);
        }
        __syncthreads();
    }

    __half* cb = ctx + (size_t)bh*DH*DH;
    #pragma unroll
    for (int mf = 0; mf < 2; mf++)
        #pragma unroll
        for (int half_ = 0; half_ < 2; half_++) {
            const int grow = d0 + m0w + mf*16 + lr + half_*8;
            #pragma unroll
            for (int nf = 0; nf < 4; nf++) {
                const int gcol = e0 + n0w + nf*8 + 2*lc;
                *(__half2*)(cb + (size_t)grow*DH + gcol) =
                    __floats2half2_rn(acc[mf][nf][half_*2], acc[mf][nf][half_*2 + 1]);
            }
        }
}

// ---------------- LayerNorm (fp32 in, fp16 out) ------------------------------
__global__ void ln_kernel(const float* __restrict__ x, const float* __restrict__ g,
                          const float* __restrict__ b, __half* __restrict__ out)
{
    __shared__ float red[16];
    __shared__ float s_mu, s_rstd;
    const int row = blockIdx.x, t = threadIdx.x;
    const float4 v = ((const float4*)(x + (size_t)row*DIM))[t];
    float s  = v.x + v.y + v.z + v.w;
    float ss = fmaf(v.x,v.x, fmaf(v.y,v.y, fmaf(v.z,v.z, v.w*v.w)));
    #pragma unroll
    for (int o = 16; o > 0; o >>= 1) {
        s  += __shfl_xor_sync(0xffffffffu, s,  o);
        ss += __shfl_xor_sync(0xffffffffu, ss, o);
    }
    const int w = t >> 5, lane = t & 31;
    if (lane == 0) { red[w] = s; red[8+w] = ss; }
    __syncthreads();
    if (t == 0) {
        float S = 0.f, SS = 0.f;
        #pragma unroll
        for (int i = 0; i < 8; i++) { S += red[i]; SS += red[8+i]; }
        float mu  = S  * (1.0f/DIM);
        float var = SS * (1.0f/DIM) - mu*mu;
        s_mu = mu; s_rstd = rsqrtf(var + 1e-5f);
    }
    __syncthreads();
    const float mu = s_mu, r = s_rstd;
    const float4 gv = ((const float4*)g)[t];
    const float4 bv = ((const float4*)b)[t];
    __half2* o2 = (__half2*)(out + (size_t)row*DIM);
    o2[t*2]   = __floats2half2_rn((v.x-mu)*r*gv.x + bv.x, (v.y-mu)*r*gv.y + bv.y);
    o2[t*2+1] = __floats2half2_rn((v.z-mu)*r*gv.z + bv.z, (v.w-mu)*r*gv.w + bv.w);
}

// ---------------- fused q softmax + k softmax partial ------------------------
// blocks [0, 8192):        qsm, 8 warps/block, row = global warp id
// blocks [8192, 8192+256): ksm_partial, idx = blockIdx.x - 8192
__global__ void qsm_ksmp(__half* __restrict__ q, const __half* __restrict__ k,
                         float* __restrict__ part)
{
    if (blockIdx.x >= 8192) {
        const int idx = blockIdx.x - 8192;
        const int ch = idx & 15, bh = idx >> 4, t = threadIdx.x;
        const __half* kp = k + ((size_t)bh*SEQ + (size_t)ch*CHUNK)*DH + t;
        float m = -INFINITY, s = 0.f;
        for (int i = 0; i < CHUNK; i++) {
            const float vv = __half2float(kp[(size_t)i*DH]) * 0.25f;
            const float nm = fmaxf(m, vv);
            s = s*expf(m - nm) + expf(vv - nm);
            m = nm;
        }
        float* pp = part + (size_t)((bh*KCH + ch)*2)*DH;
        pp[t] = m; pp[DH + t] = s;
        return;
    }
    const int warp = (blockIdx.x * blockDim.x + threadIdx.x) >> 5;
    const int lane = threadIdx.x & 31;
    __half* row = q + (size_t)warp * DH;
    float v[8];
    float m = -INFINITY;
    #pragma unroll
    for (int j = 0; j < 8; j++) {
        v[j] = __half2float(row[j*32 + lane]) * 0.25f;
        m = fmaxf(m, v[j]);
    }
    #pragma unroll
    for (int o = 16; o > 0; o >>= 1) m = fmaxf(m, __shfl_xor_sync(0xffffffffu, m, o));
    float s = 0.f;
    #pragma unroll
    for (int j = 0; j < 8; j++) { v[j] = expf(v[j] - m); s += v[j]; }
    #pragma unroll
    for (int o = 16; o > 0; o >>= 1) s += __shfl_xor_sync(0xffffffffu, s, o);
    const float inv = 1.0f / s;
    #pragma unroll
    for (int j = 0; j < 8; j++) row[j*32 + lane] = __float2half_rn(v[j] * inv);
}

__global__ void ksm_norm(__half* __restrict__ k, const float* __restrict__ part)
{
    const int bh = blockIdx.y, ch = blockIdx.x, t = threadIdx.x;
    float M = -INFINITY;
    #pragma unroll
    for (int c = 0; c < KCH; c++)
        M = fmaxf(M, part[(size_t)((bh*KCH + c)*2)*DH + t]);
    float S = 0.f;
    #pragma unroll
    for (int c = 0; c < KCH; c++) {
        const float* pp = part + (size_t)((bh*KCH + c)*2)*DH;
        S += pp[DH + t] * expf(pp[t] - M);
    }
    const float inv = 1.0f / S;
    __half* kp = k + ((size_t)bh*SEQ + (size_t)ch*CHUNK)*DH + t;
    for (int i = 0; i < CHUNK; i++) {
        const float vv = __half2float(kp[(size_t)i*DH]) * 0.25f;
        kp[(size_t)i*DH] = __float2half_rn(expf(vv - M) * inv);
    }
}

// ---------------- launch ----------------------------------------------------
extern "C" void kernel_launch(void* const* d_in, const int* in_sizes, int n_in,
                              void* d_out, int out_size)
{
    const float* x    = (const float*)d_in[0];
    const float* ln1g = (const float*)d_in[1];
    const float* ln1b = (const float*)d_in[2];
    const float* wq   = (const float*)d_in[3];
    const float* wk   = (const float*)d_in[4];
    const float* wv   = (const float*)d_in[5];
    const float* wo   = (const float*)d_in[6];
    const float* bo   = (const float*)d_in[7];
    const float* ln2g = (const float*)d_in[8];
    const float* ln2b = (const float*)d_in[9];
    const float* wff1 = (const float*)d_in[10];
    const float* bff1 = (const float*)d_in[11];
    const float* wff2 = (const float*)d_in[12];
    const float* bff2 = (const float*)d_in[13];
    const float* wd   = (const float*)d_in[14];
    const float* bd   = (const float*)d_in[15];
    float* out = (float*)d_out;

    float *x1,*part;
    __half *h,*qh,*kh,*vh,*ctxh,*w2h,*ffh,*x2h,*wr;
    cudaGetSymbolAddress((void**)&x1,   g_x1);
    cudaGetSymbolAddress((void**)&part, g_part);
    cudaGetSymbolAddress((void**)&h,    g_h);
    cudaGetSymbolAddress((void**)&qh,   g_qh);
    cudaGetSymbolAddress((void**)&kh,   g_kh);
    cudaGetSymbolAddress((void**)&vh,   g_vh);
    cudaGetSymbolAddress((void**)&ctxh, g_ctxh);
    cudaGetSymbolAddress((void**)&w2h,  g_w2h);
    cudaGetSymbolAddress((void**)&ffh,  g_ffh);
    cudaGetSymbolAddress((void**)&x2h,  g_x2h);
    cudaGetSymbolAddress((void**)&wr,   g_wr);

    cudaFuncSetAttribute(gemm_mma<0>, cudaFuncAttributeMaxDynamicSharedMemorySize, SMEM3);
    cudaFuncSetAttribute(gemm_mma<2>, cudaFuncAttributeMaxDynamicSharedMemorySize, SMEM3);
    cudaFuncSetAttribute(gemm_mma<5>, cudaFuncAttributeMaxDynamicSharedMemorySize, SMEM3);
    cudaFuncSetAttribute(gemm_mma<7>, cudaFuncAttributeMaxDynamicSharedMemorySize, SMEM3);
    cudaFuncSetAttribute(gemm_mma<8>, cudaFuncAttributeMaxDynamicSharedMemorySize, SMEM3);
    cudaFuncSetAttribute(gemm_mma<9>, cudaFuncAttributeMaxDynamicSharedMemorySize, SMEM3);

    // --- attention block (ln1 runs concurrently with weight conversion) ---
    ln1_cvt<<<TOK + NCVT, 256>>>(x, ln1g, ln1b, h,
                                 wq, wk, wv, wo, wd, wff1, wff2, wr);
    gemm_mma<7><<<dim3(24, 128), 256, SMEM3>>>(h, wr + OFF_QKV,
                                               (const float*)kh, (const float*)vh,
                                               qh, 3*DIM, DIM);
    qsm_ksmp<<<8192 + 256, 256>>>(qh, kh, part);
    ksm_norm<<<dim3(KCH, NBH), 256>>>(kh, part);
    ctx_mma <<<dim3(4, 4, NBH), 128>>>(kh, vh, ctxh);
    gemm_mma<8><<<dim3(8, 2, NBH), 256, SMEM3>>>(ctxh, wr + OFF_WO, nullptr, nullptr,
                                                 w2h, DIM, DH);
    gemm_mma<9><<<dim3(8, 32, BATCH), 256, SMEM3>>>(qh, w2h, bo, x, x1, DIM, DIM);

    // --- FFN block ---
    ln_kernel<<<TOK, 256>>>(x1, ln2g, ln2b, h);
    gemm_mma<2><<<dim3(32, 128), 256, SMEM3>>>(h, wr + OFF_WFF1, bff1, nullptr, ffh, FFD, DIM);
    gemm_mma<5><<<dim3(8, 128), 256, SMEM3>>>(ffh, wr + OFF_WFF2, bff2, x1, x2h, DIM, FFD);

    // --- trailing dense ---
    gemm_mma<0><<<dim3(8, 128), 256, SMEM3>>>(x2h, wr + OFF_WD, bd, nullptr, out, DIM, DIM);
}

// round 16
// speedup vs baseline: 1.0149x; 1.0036x over previous
#include <cuda_runtime.h>
#include <cuda_fp16.h>
#include <math.h>
#include <stdint.h>

#define BATCH 4
#define SEQ   4096
#define DIM   1024
#define NH    4
#define DH    256
#define FFD   4096
#define TOK   (BATCH*SEQ)   /* 16384 */
#define NBH   (BATCH*NH)    /* 16 */
#define KCH   16
#define CHUNK (SEQ/KCH)     /* 256 */

/* fp16 mma GEMM tiling: 128x128 CTA tile, 256 threads, 8 warps of 64x32 */
#define TM 128
#define TN 128
#define TK 64
#define APITCH 72
#define BPITCH 136
#define ABYTES (TM*APITCH*2)        /* 18432 */
#define BBYTES (TK*BPITCH*2)        /* 17408 */
#define STAGEB (ABYTES+BBYTES)      /* 35840 */
#define SMEM3  (3*STAGEB)           /* 107520: 2 CTAs/SM = 210KB < 228KB */

/* ctx mma tiling: 64x64 tiles, 128 threads, 4 warps of 32x32 */
#define CTK 64
#define CPITCH 72

// ---------------- scratch ---------------------------------------------------
__device__ float  g_x1  [(size_t)TOK*DIM];
__device__ float  g_part[NBH*KCH*2*DH];
__device__ __half g_h   [(size_t)TOK*DIM];
__device__ __half g_qh  [(size_t)TOK*DIM];      /* q token-major [b,n,h,dh] */
__device__ __half g_kh  [(size_t)NBH*SEQ*DH];
__device__ __half g_vh  [(size_t)NBH*SEQ*DH];
__device__ __half g_ctxh[(size_t)NBH*DH*DH];
__device__ __half g_w2h [(size_t)BATCH*DIM*DIM]; /* W2_b = blockdiag(ctx_{b,h}) @ wo */
__device__ __half g_ffh [(size_t)TOK*FFD];
__device__ __half g_x2h [(size_t)TOK*DIM];
__device__ __half g_wr  [(size_t)13*1024*1024];

/* offsets into g_wr (halves) */
#define OFF_QKV  (0)                 /* packed [1024][3072]: wq|wk|wv */
#define OFF_WO   (3*1024*1024)
#define OFF_WD   (4*1024*1024)
#define OFF_WFF1 (5*1024*1024)
#define OFF_WFF2 (9*1024*1024)

__device__ __forceinline__ float gelu_tanh(float x) {
    float x3 = x*x*x;
    return 0.5f*x*(1.0f + tanhf(0.7978845608028654f*(x + 0.044715f*x3)));
}
__device__ __forceinline__ uint32_t smem_u32(const void* p) {
    uint32_t a;
    asm("{ .reg .u64 t; cvta.to.shared.u64 t, %1; cvt.u32.u64 %0, t; }" : "=r"(a) : "l"(p));
    return a;
}
__device__ __forceinline__ void cp16(uint32_t dst, const void* src) {
    asm volatile("cp.async.cg.shared.global [%0], [%1], 16;" :: "r"(dst), "l"(src));
}
__device__ __forceinline__ void ldm_x4(uint32_t* r, uint32_t addr) {
    asm volatile("ldmatrix.sync.aligned.m8n8.x4.shared.b16 {%0,%1,%2,%3}, [%4];"
        : "=r"(r[0]), "=r"(r[1]), "=r"(r[2]), "=r"(r[3]) : "r"(addr));
}
__device__ __forceinline__ void ldm_x4_t(uint32_t* r, uint32_t addr) {
    asm volatile("ldmatrix.sync.aligned.m8n8.x4.trans.shared.b16 {%0,%1,%2,%3}, [%4];"
        : "=r"(r[0]), "=r"(r[1]), "=r"(r[2]), "=r"(r[3]) : "r"(addr));
}
__device__ __forceinline__ void mma_f16(float* c, uint32_t a0, uint32_t a1, uint32_t a2,
                                        uint32_t a3, uint32_t b0, uint32_t b1) {
    asm volatile("mma.sync.aligned.m16n8k16.row.col.f32.f16.f16.f32 "
        "{%0,%1,%2,%3}, {%4,%5,%6,%7}, {%8,%9}, {%0,%1,%2,%3};"
        : "+f"(c[0]), "+f"(c[1]), "+f"(c[2]), "+f"(c[3])
        : "r"(a0), "r"(a1), "r"(a2), "r"(a3), "r"(b0), "r"(b1));
}

// ---------------- fused ln1 + weight conversion ------------------------------
#define D4 262144
#define F4 1048576
#define NCVT ((5*D4 + 2*F4)/256)     /* 13312 */
__global__ void ln1_cvt(const float* __restrict__ x, const float* __restrict__ g,
                        const float* __restrict__ b, __half* __restrict__ out,
                        const float* __restrict__ wq, const float* __restrict__ wk,
                        const float* __restrict__ wv, const float* __restrict__ wo,
                        const float* __restrict__ wd, const float* __restrict__ wff1,
                        const float* __restrict__ wff2, __half* __restrict__ wr)
{
    const int t = threadIdx.x;
    if (blockIdx.x >= TOK) {
        const int i = (blockIdx.x - TOK) * 256 + t;
        const float* src;
        __half2* d2;
        if (i < 3*D4) {
            const int m = i / D4, j = i % D4;
            src = (m == 0) ? wq : (m == 1) ? wk : wv;
            const int row = j >> 8, c4 = j & 255;
            float4 v = ((const float4*)src)[j];
            d2 = (__half2*)(wr + OFF_QKV + (size_t)row*3072 + m*1024 + c4*4);
            d2[0] = __floats2half2_rn(v.x, v.y);
            d2[1] = __floats2half2_rn(v.z, v.w);
            return;
        }
        int j; size_t off;
        if      (i < 4*D4)      { j = i - 3*D4;      src = wo;   off = OFF_WO; }
        else if (i < 5*D4)      { j = i - 4*D4;      src = wd;   off = OFF_WD; }
        else if (i < 5*D4 + F4) { j = i - 5*D4;      src = wff1; off = OFF_WFF1; }
        else                    { j = i - 5*D4 - F4; src = wff2; off = OFF_WFF2; }
        float4 v = ((const float4*)src)[j];
        d2 = (__half2*)(wr + off + (size_t)j*4);
        d2[0] = __floats2half2_rn(v.x, v.y);
        d2[1] = __floats2half2_rn(v.z, v.w);
        return;
    }
    __shared__ float red[16];
    __shared__ float s_mu, s_rstd;
    const int row = blockIdx.x;
    const float4 v = ((const float4*)(x + (size_t)row*DIM))[t];
    float s  = v.x + v.y + v.z + v.w;
    float ss = fmaf(v.x,v.x, fmaf(v.y,v.y, fmaf(v.z,v.z, v.w*v.w)));
    #pragma unroll
    for (int o = 16; o > 0; o >>= 1) {
        s  += __shfl_xor_sync(0xffffffffu, s,  o);
        ss += __shfl_xor_sync(0xffffffffu, ss, o);
    }
    const int w = t >> 5, lane = t & 31;
    if (lane == 0) { red[w] = s; red[8+w] = ss; }
    __syncthreads();
    if (t == 0) {
        float S = 0.f, SS = 0.f;
        #pragma unroll
        for (int i = 0; i < 8; i++) { S += red[i]; SS += red[8+i]; }
        float mu  = S  * (1.0f/DIM);
        float var = SS * (1.0f/DIM) - mu*mu;
        s_mu = mu; s_rstd = rsqrtf(var + 1e-5f);
    }
    __syncthreads();
    const float mu = s_mu, r = s_rstd;
    const float4 gv = ((const float4*)g)[t];
    const float4 bv = ((const float4*)b)[t];
    __half2* o2 = (__half2*)(out + (size_t)row*DIM);
    o2[t*2]   = __floats2half2_rn((v.x-mu)*r*gv.x + bv.x, (v.y-mu)*r*gv.y + bv.y);
    o2[t*2+1] = __floats2half2_rn((v.z-mu)*r*gv.z + bv.z, (v.w-mu)*r*gv.w + bv.w);
}

// ---------------- fp16 mma GEMM, 128x128 tiles, 3-stage, 1 bar/iter ----------
// MODE 0: C(fp32) = acc + bias
// MODE 2: C(fp16) = gelu(acc + bias)
// MODE 5: C(fp16) = acc + bias + res
// MODE 7: fused qkv: W=[1024][3072]; q -> Cv row-major [TOK][1024];
//         k -> bias cast scatter [b,h,n,dh]; v -> res cast scatter
// MODE 8: W2 batch z=bh: A=ctx+z*DH*DH, W=wo+(z&3)*DH*Ncols,
//         C(fp16) at w2 + (z>>2)*DIM*Ncols + (z&3)*DH*Ncols
// MODE 9: batched over z=b: A=qh+z*SEQ*K, W=w2+z*K*Ncols, res/C + z*SEQ*Ncols
template<int MODE>
__global__ void __launch_bounds__(256, 2)
gemm_mma(const __half* __restrict__ A, const __half* __restrict__ W,
         const float* __restrict__ bias, const float* __restrict__ res,
         void* __restrict__ Cv, int Ncols, int K)
{
    extern __shared__ char dsm[];
    uint32_t aAs[3], aBs[3];
    #pragma unroll
    for (int s = 0; s < 3; s++) {
        aAs[s] = smem_u32(dsm + s*STAGEB);
        aBs[s] = smem_u32(dsm + s*STAGEB + ABYTES);
    }

    size_t cofs = 0;
    if (MODE == 8) {
        const int z = blockIdx.z;
        A += (size_t)z * DH * DH;
        W += (size_t)(z & 3) * DH * Ncols;
        cofs = (size_t)(z >> 2) * DIM * Ncols + (size_t)(z & 3) * DH * Ncols;
    }
    if (MODE == 9) {
        const int z = blockIdx.z;
        A += (size_t)z * SEQ * K;
        W += (size_t)z * K * Ncols;
        res += (size_t)z * SEQ * Ncols;
        cofs = (size_t)z * SEQ * Ncols;
    }

    const int tid  = threadIdx.x;
    const int lane = tid & 31;
    const int w    = tid >> 5;
    const int m0w  = (w >> 2) * 64;
    const int n0w  = (w & 3) * 32;
    const int row0 = blockIdx.y * TM;
    const int col0 = blockIdx.x * TN;
    const int NT   = K / TK;

    const int lr = lane >> 2;
    const int lc = lane & 3;
    const int l15 = lane & 15;
    const int lhi8 = (lane >> 4) * 8;

    auto fill = [&](int buf, int k0) {
        #pragma unroll
        for (int j = 0; j < 4; j++) {
            int f  = tid + 256*j;
            int r  = f >> 3, c8 = f & 7;
            cp16(aAs[buf] + (uint32_t)(r*APITCH + c8*8)*2,
                 A + (size_t)(row0 + r)*K + k0 + c8*8);
        }
        #pragma unroll
        for (int j = 0; j < 4; j++) {
            int f  = tid + 256*j;
            int kr = f >> 4, c8 = f & 15;
            cp16(aBs[buf] + (uint32_t)(kr*BPITCH + c8*8)*2,
                 W + (size_t)(k0 + kr)*Ncols + col0 + c8*8);
        }
        asm volatile("cp.async.commit_group;");
    };

    float acc[4][4][4];
    #pragma unroll
    for (int i = 0; i < 4; i++)
        #pragma unroll
        for (int j = 0; j < 4; j++)
            #pragma unroll
            for (int r = 0; r < 4; r++) acc[i][j][r] = 0.f;

    fill(0, 0);
    fill(1, TK);

    int buf = 0;
    for (int t = 0; t < NT; t++) {
        if (t + 1 < NT) asm volatile("cp.async.wait_group 1;");
        else            asm volatile("cp.async.wait_group 0;");
        __syncthreads();
        if (t + 2 < NT) fill((t + 2) % 3, (t + 2) * TK);

        const uint32_t a_lm = aAs[buf] + (uint32_t)((m0w + l15)*APITCH + lhi8)*2;
        const uint32_t b_lm = aBs[buf] + (uint32_t)(l15*BPITCH + n0w + lhi8)*2;

        #pragma unroll
        for (int kk = 0; kk < 4; kk++) {
            uint32_t af[4][4];
            #pragma unroll
            for (int mf = 0; mf < 4; mf++)
                ldm_x4(af[mf], a_lm + (uint32_t)(mf*16*APITCH + kk*16)*2);

            uint32_t bf[2][4];
            #pragma unroll
            for (int np = 0; np < 2; np++)
                ldm_x4_t(bf[np], b_lm + (uint32_t)(kk*16*BPITCH + np*16)*2);

            #pragma unroll
            for (int mf = 0; mf < 4; mf++)
                #pragma unroll
                for (int nf = 0; nf < 4; nf++)
                    mma_f16(acc[mf][nf],
                            af[mf][0], af[mf][1], af[mf][2], af[mf][3],
                            bf[nf >> 1][(nf & 1)*2], bf[nf >> 1][(nf & 1)*2 + 1]);
        }
        buf = (buf + 1 == 3) ? 0 : buf + 1;
    }

    // ---- epilogue ----
    float*  Cf = (float*)Cv;
    __half* Ch = (__half*)Cv;
    #pragma unroll
    for (int mf = 0; mf < 4; mf++) {
        #pragma unroll
        for (int half_ = 0; half_ < 2; half_++) {
            const int grow = row0 + m0w + mf*16 + lr + half_*8;
            #pragma unroll
            for (int nf = 0; nf < 4; nf++) {
                const int gcol = col0 + n0w + nf*8 + 2*lc;
                float v0 = acc[mf][nf][half_*2 + 0];
                float v1 = acc[mf][nf][half_*2 + 1];
                if (MODE == 7) {
                    const int mat  = gcol >> 10;
                    const int hcol = gcol & 1023;
                    if (mat == 0) {
                        *(__half2*)(Ch + (size_t)grow*DIM + hcol) = __floats2half2_rn(v0, v1);
                    } else {
                        const int head = hcol >> 8;
                        const int dh0  = hcol & 255;
                        const int b_   = grow >> 12;
                        const int n_   = grow & 4095;
                        const size_t off = ((size_t)((b_*NH + head)*SEQ + n_))*DH + dh0;
                        __half* dst = (mat == 1) ? (__half*)bias : (__half*)res;
                        *(__half2*)(dst + off) = __floats2half2_rn(v0, v1);
                    }
                } else if (MODE == 8) {
                    *(__half2*)(Ch + cofs + (size_t)grow*Ncols + gcol) = __floats2half2_rn(v0, v1);
                } else {
                    v0 += bias[gcol];
                    v1 += bias[gcol + 1];
                    if (MODE == 2) { v0 = gelu_tanh(v0); v1 = gelu_tanh(v1); }
                    if (MODE == 5 || MODE == 9) {
                        const float2 rv = *(const float2*)(res + (size_t)grow*Ncols + gcol);
                        v0 += rv.x; v1 += rv.y;
                    }
                    if (MODE == 2 || MODE == 5) {
                        *(__half2*)(Ch + (size_t)grow*Ncols + gcol) = __floats2half2_rn(v0, v1);
                    } else {
                        *(float2*)(Cf + cofs + (size_t)grow*Ncols + gcol) = make_float2(v0, v1);
                    }
                }
            }
        }
    }
}

// ---------------- ctx = k^T @ v (fp16 mma, both operands transposed) --------
__global__ void __launch_bounds__(128, 2)
ctx_mma(const __half* __restrict__ kh, const __half* __restrict__ vh,
        __half* __restrict__ ctx)
{
    __shared__ __half Ks[2][CTK][CPITCH];
    __shared__ __half Vs[2][CTK][CPITCH];
    const int bh = blockIdx.z;
    const int d0 = blockIdx.y * 64, e0 = blockIdx.x * 64;
    const __half* kb = kh + (size_t)bh*SEQ*DH;
    const __half* vb = vh + (size_t)bh*SEQ*DH;
    const int tid = threadIdx.x, lane = tid & 31, w = tid >> 5;
    const int m0w = (w >> 1) * 32, n0w = (w & 1) * 32;

    const uint32_t kbase[2] = { smem_u32(&Ks[0][0][0]), smem_u32(&Ks[1][0][0]) };
    const uint32_t vbase[2] = { smem_u32(&Vs[0][0][0]), smem_u32(&Vs[1][0][0]) };

    auto fill = [&](int buf, int n0) {
        #pragma unroll
        for (int j = 0; j < 4; j++) {
            int f = tid + 128*j;
            int r = f >> 3, c8 = f & 7;
            cp16(kbase[buf] + (uint32_t)(r*CPITCH + c8*8)*2, kb + (size_t)(n0+r)*DH + d0 + c8*8);
            cp16(vbase[buf] + (uint32_t)(r*CPITCH + c8*8)*2, vb + (size_t)(n0+r)*DH + e0 + c8*8);
        }
        asm volatile("cp.async.commit_group;");
    };

    float acc[2][4][4];
    #pragma unroll
    for (int i = 0; i < 2; i++)
        #pragma unroll
        for (int j = 0; j < 4; j++)
            #pragma unroll
            for (int r = 0; r < 4; r++) acc[i][j][r] = 0.f;

    const int arow = (lane & 7) + ((lane >> 4) << 3);
    const int acol = ((lane >> 3) & 1) * 8;
    const int l15 = lane & 15, lhi8 = (lane >> 4) * 8;
    const int lr = lane >> 2, lc = lane & 3;

    fill(0, 0);
    const int NTc = SEQ / CTK;
    for (int t = 0; t < NTc; t++) {
        if (t + 1 < NTc) {
            fill((t + 1) & 1, (t + 1) * CTK);
            asm volatile("cp.async.wait_group 1;");
        } else {
            asm volatile("cp.async.wait_group 0;");
        }
        __syncthreads();
        const uint32_t ka = kbase[t & 1];
        const uint32_t va = vbase[t & 1];

        #pragma unroll
        for (int kk = 0; kk < 4; kk++) {
            uint32_t af[2][4];
            #pragma unroll
            for (int mf = 0; mf < 2; mf++)
                ldm_x4_t(af[mf], ka + (uint32_t)((kk*16 + arow)*CPITCH + m0w + mf*16 + acol)*2);
            uint32_t bf[2][4];
            #pragma unroll
            for (int np = 0; np < 2; np++)
                ldm_x4_t(bf[np], va + (uint32_t)((kk*16 + l15)*CPITCH + n0w + np*16 + lhi8)*2);
            #pragma unroll
            for (int mf = 0; mf < 2; mf++)
                #pragma unroll
                for (int nf = 0; nf < 4; nf++)
                    mma_f16(acc[mf][nf],
                            af[mf][0], af[mf][1], af[mf][2], af[mf][3],
                            bf[nf >> 1][(nf & 1)*2], bf[nf >> 1][(nf & 1)*2 + 1]);
        }
        __syncthreads();
    }

    __half* cb = ctx + (size_t)bh*DH*DH;
    #pragma unroll
    for (int mf = 0; mf < 2; mf++)
        #pragma unroll
        for (int half_ = 0; half_ < 2; half_++) {
            const int grow = d0 + m0w + mf*16 + lr + half_*8;
            #pragma unroll
            for (int nf = 0; nf < 4; nf++) {
                const int gcol = e0 + n0w + nf*8 + 2*lc;
                *(__half2*)(cb + (size_t)grow*DH + gcol) =
                    __floats2half2_rn(acc[mf][nf][half_*2], acc[mf][nf][half_*2 + 1]);
            }
        }
}

// ---------------- LayerNorm (fp32 in, fp16 out) ------------------------------
__global__ void ln_kernel(const float* __restrict__ x, const float* __restrict__ g,
                          const float* __restrict__ b, __half* __restrict__ out)
{
    __shared__ float red[16];
    __shared__ float s_mu, s_rstd;
    const int row = blockIdx.x, t = threadIdx.x;
    const float4 v = ((const float4*)(x + (size_t)row*DIM))[t];
    float s  = v.x + v.y + v.z + v.w;
    float ss = fmaf(v.x,v.x, fmaf(v.y,v.y, fmaf(v.z,v.z, v.w*v.w)));
    #pragma unroll
    for (int o = 16; o > 0; o >>= 1) {
        s  += __shfl_xor_sync(0xffffffffu, s,  o);
        ss += __shfl_xor_sync(0xffffffffu, ss, o);
    }
    const int w = t >> 5, lane = t & 31;
    if (lane == 0) { red[w] = s; red[8+w] = ss; }
    __syncthreads();
    if (t == 0) {
        float S = 0.f, SS = 0.f;
        #pragma unroll
        for (int i = 0; i < 8; i++) { S += red[i]; SS += red[8+i]; }
        float mu  = S  * (1.0f/DIM);
        float var = SS * (1.0f/DIM) - mu*mu;
        s_mu = mu; s_rstd = rsqrtf(var + 1e-5f);
    }
    __syncthreads();
    const float mu = s_mu, r = s_rstd;
    const float4 gv = ((const float4*)g)[t];
    const float4 bv = ((const float4*)b)[t];
    __half2* o2 = (__half2*)(out + (size_t)row*DIM);
    o2[t*2]   = __floats2half2_rn((v.x-mu)*r*gv.x + bv.x, (v.y-mu)*r*gv.y + bv.y);
    o2[t*2+1] = __floats2half2_rn((v.z-mu)*r*gv.z + bv.z, (v.w-mu)*r*gv.w + bv.w);
}

// ---------------- fused q softmax + k softmax partial ------------------------
__global__ void qsm_ksmp(__half* __restrict__ q, const __half* __restrict__ k,
                         float* __restrict__ part)
{
    if (blockIdx.x >= 8192) {
        const int idx = blockIdx.x - 8192;
        const int ch = idx & 15, bh = idx >> 4, t = threadIdx.x;
        const __half* kp = k + ((size_t)bh*SEQ + (size_t)ch*CHUNK)*DH + t;
        float m = -INFINITY, s = 0.f;
        for (int i = 0; i < CHUNK; i++) {
            const float vv = __half2float(kp[(size_t)i*DH]) * 0.25f;
            const float nm = fmaxf(m, vv);
            s = s*expf(m - nm) + expf(vv - nm);
            m = nm;
        }
        float* pp = part + (size_t)((bh*KCH + ch)*2)*DH;
        pp[t] = m; pp[DH + t] = s;
        return;
    }
    const int warp = (blockIdx.x * blockDim.x + threadIdx.x) >> 5;
    const int lane = threadIdx.x & 31;
    __half* row = q + (size_t)warp * DH;
    float v[8];
    float m = -INFINITY;
    #pragma unroll
    for (int j = 0; j < 8; j++) {
        v[j] = __half2float(row[j*32 + lane]) * 0.25f;
        m = fmaxf(m, v[j]);
    }
    #pragma unroll
    for (int o = 16; o > 0; o >>= 1) m = fmaxf(m, __shfl_xor_sync(0xffffffffu, m, o));
    float s = 0.f;
    #pragma unroll
    for (int j = 0; j < 8; j++) { v[j] = expf(v[j] - m); s += v[j]; }
    #pragma unroll
    for (int o = 16; o > 0; o >>= 1) s += __shfl_xor_sync(0xffffffffu, s, o);
    const float inv = 1.0f / s;
    #pragma unroll
    for (int j = 0; j < 8; j++) row[j*32 + lane] = __float2half_rn(v[j] * inv);
}

// ---------------- k softmax normalize, 4x parallel over quarter-chunks ------
__global__ void ksm_norm(__half* __restrict__ k, const float* __restrict__ part)
{
    const int bh = blockIdx.y;
    const int ch = blockIdx.x >> 2;         /* chunk 0..15 */
    const int qu = blockIdx.x & 3;          /* quarter 0..3 */
    const int t  = threadIdx.x;
    float M = -INFINITY;
    #pragma unroll
    for (int c = 0; c < KCH; c++)
        M = fmaxf(M, part[(size_t)((bh*KCH + c)*2)*DH + t]);
    float S = 0.f;
    #pragma unroll
    for (int c = 0; c < KCH; c++) {
        const float* pp = part + (size_t)((bh*KCH + c)*2)*DH;
        S += pp[DH + t] * expf(pp[t] - M);
    }
    const float inv = 1.0f / S;
    __half* kp = k + ((size_t)bh*SEQ + (size_t)ch*CHUNK + (size_t)qu*(CHUNK/4))*DH + t;
    #pragma unroll 4
    for (int i = 0; i < CHUNK/4; i++) {
        const float vv = __half2float(kp[(size_t)i*DH]) * 0.25f;
        kp[(size_t)i*DH] = __float2half_rn(expf(vv - M) * inv);
    }
}

// ---------------- launch ----------------------------------------------------
extern "C" void kernel_launch(void* const* d_in, const int* in_sizes, int n_in,
                              void* d_out, int out_size)
{
    const float* x    = (const float*)d_in[0];
    const float* ln1g = (const float*)d_in[1];
    const float* ln1b = (const float*)d_in[2];
    const float* wq   = (const float*)d_in[3];
    const float* wk   = (const float*)d_in[4];
    const float* wv   = (const float*)d_in[5];
    const float* wo   = (const float*)d_in[6];
    const float* bo   = (const float*)d_in[7];
    const float* ln2g = (const float*)d_in[8];
    const float* ln2b = (const float*)d_in[9];
    const float* wff1 = (const float*)d_in[10];
    const float* bff1 = (const float*)d_in[11];
    const float* wff2 = (const float*)d_in[12];
    const float* bff2 = (const float*)d_in[13];
    const float* wd   = (const float*)d_in[14];
    const float* bd   = (const float*)d_in[15];
    float* out = (float*)d_out;

    float *x1,*part;
    __half *h,*qh,*kh,*vh,*ctxh,*w2h,*ffh,*x2h,*wr;
    cudaGetSymbolAddress((void**)&x1,   g_x1);
    cudaGetSymbolAddress((void**)&part, g_part);
    cudaGetSymbolAddress((void**)&h,    g_h);
    cudaGetSymbolAddress((void**)&qh,   g_qh);
    cudaGetSymbolAddress((void**)&kh,   g_kh);
    cudaGetSymbolAddress((void**)&vh,   g_vh);
    cudaGetSymbolAddress((void**)&ctxh, g_ctxh);
    cudaGetSymbolAddress((void**)&w2h,  g_w2h);
    cudaGetSymbolAddress((void**)&ffh,  g_ffh);
    cudaGetSymbolAddress((void**)&x2h,  g_x2h);
    cudaGetSymbolAddress((void**)&wr,   g_wr);

    cudaFuncSetAttribute(gemm_mma<0>, cudaFuncAttributeMaxDynamicSharedMemorySize, SMEM3);
    cudaFuncSetAttribute(gemm_mma<2>, cudaFuncAttributeMaxDynamicSharedMemorySize, SMEM3);
    cudaFuncSetAttribute(gemm_mma<5>, cudaFuncAttributeMaxDynamicSharedMemorySize, SMEM3);
    cudaFuncSetAttribute(gemm_mma<7>, cudaFuncAttributeMaxDynamicSharedMemorySize, SMEM3);
    cudaFuncSetAttribute(gemm_mma<8>, cudaFuncAttributeMaxDynamicSharedMemorySize, SMEM3);
    cudaFuncSetAttribute(gemm_mma<9>, cudaFuncAttributeMaxDynamicSharedMemorySize, SMEM3);

    // --- attention block (ln1 runs concurrently with weight conversion) ---
    ln1_cvt<<<TOK + NCVT, 256>>>(x, ln1g, ln1b, h,
                                 wq, wk, wv, wo, wd, wff1, wff2, wr);
    gemm_mma<7><<<dim3(24, 128), 256, SMEM3>>>(h, wr + OFF_QKV,
                                               (const float*)kh, (const float*)vh,
                                               qh, 3*DIM, DIM);
    qsm_ksmp<<<8192 + 256, 256>>>(qh, kh, part);
    ksm_norm<<<dim3(KCH*4, NBH), 256>>>(kh, part);
    ctx_mma <<<dim3(4, 4, NBH), 128>>>(kh, vh, ctxh);
    gemm_mma<8><<<dim3(8, 2, NBH), 256, SMEM3>>>(ctxh, wr + OFF_WO, nullptr, nullptr,
                                                 w2h, DIM, DH);
    gemm_mma<9><<<dim3(8, 32, BATCH), 256, SMEM3>>>(qh, w2h, bo, x, x1, DIM, DIM);

    // --- FFN block ---
    ln_kernel<<<TOK, 256>>>(x1, ln2g, ln2b, h);
    gemm_mma<2><<<dim3(32, 128), 256, SMEM3>>>(h, wr + OFF_WFF1, bff1, nullptr, ffh, FFD, DIM);
    gemm_mma<5><<<dim3(8, 128), 256, SMEM3>>>(ffh, wr + OFF_WFF2, bff2, x1, x2h, DIM, FFD);

    // --- trailing dense ---
    gemm_mma<0><<<dim3(8, 128), 256, SMEM3>>>(x2h, wr + OFF_WD, bd, nullptr, out, DIM, DIM);
}

// round 17
// speedup vs baseline: 1.0181x; 1.0031x over previous
#include <cuda_runtime.h>
#include <cuda_fp16.h>
#include <math.h>
#include <stdint.h>

#define BATCH 4
#define SEQ   4096
#define DIM   1024
#define NH    4
#define DH    256
#define FFD   4096
#define TOK   (BATCH*SEQ)   /* 16384 */
#define NBH   (BATCH*NH)    /* 16 */
#define KCH   16
#define CHUNK (SEQ/KCH)     /* 256 */

/* fp16 mma GEMM tiling: 128x128 CTA tile, 256 threads, 8 warps of 64x32 */
#define TM 128
#define TN 128
#define TK 64
#define APITCH 72
#define BPITCH 136
#define ABYTES (TM*APITCH*2)        /* 18432 */
#define BBYTES (TK*BPITCH*2)        /* 17408 */
#define STAGEB (ABYTES+BBYTES)      /* 35840 */
#define SMEM3  (3*STAGEB)           /* 107520: 2 CTAs/SM = 210KB < 228KB */

/* ctx mma tiling: 64x64 tiles, 128 threads, 4 warps of 32x32 */
#define CTK 64
#define CPITCH 72

// ---------------- scratch ---------------------------------------------------
__device__ float  g_part[NBH*KCH*2*DH];
__device__ __half g_x1h [(size_t)TOK*DIM];      /* attention-block residual, fp16 */
__device__ __half g_h   [(size_t)TOK*DIM];
__device__ __half g_qh  [(size_t)TOK*DIM];      /* q token-major [b,n,h,dh] */
__device__ __half g_kh  [(size_t)NBH*SEQ*DH];
__device__ __half g_vh  [(size_t)NBH*SEQ*DH];
__device__ __half g_ctxh[(size_t)NBH*DH*DH];
__device__ __half g_w2h [(size_t)BATCH*DIM*DIM]; /* W2_b = blockdiag(ctx_{b,h}) @ wo */
__device__ __half g_ffh [(size_t)TOK*FFD];
__device__ __half g_x2h [(size_t)TOK*DIM];
__device__ __half g_wr  [(size_t)13*1024*1024];

/* offsets into g_wr (halves) */
#define OFF_QKV  (0)                 /* packed [1024][3072]: wq|wk|wv */
#define OFF_WO   (3*1024*1024)
#define OFF_WD   (4*1024*1024)
#define OFF_WFF1 (5*1024*1024)
#define OFF_WFF2 (9*1024*1024)

__device__ __forceinline__ float gelu_tanh(float x) {
    float x3 = x*x*x;
    return 0.5f*x*(1.0f + tanhf(0.7978845608028654f*(x + 0.044715f*x3)));
}
__device__ __forceinline__ uint32_t smem_u32(const void* p) {
    uint32_t a;
    asm("{ .reg .u64 t; cvta.to.shared.u64 t, %1; cvt.u32.u64 %0, t; }" : "=r"(a) : "l"(p));
    return a;
}
__device__ __forceinline__ void cp16(uint32_t dst, const void* src) {
    asm volatile("cp.async.cg.shared.global [%0], [%1], 16;" :: "r"(dst), "l"(src));
}
__device__ __forceinline__ void ldm_x4(uint32_t* r, uint32_t addr) {
    asm volatile("ldmatrix.sync.aligned.m8n8.x4.shared.b16 {%0,%1,%2,%3}, [%4];"
        : "=r"(r[0]), "=r"(r[1]), "=r"(r[2]), "=r"(r[3]) : "r"(addr));
}
__device__ __forceinline__ void ldm_x4_t(uint32_t* r, uint32_t addr) {
    asm volatile("ldmatrix.sync.aligned.m8n8.x4.trans.shared.b16 {%0,%1,%2,%3}, [%4];"
        : "=r"(r[0]), "=r"(r[1]), "=r"(r[2]), "=r"(r[3]) : "r"(addr));
}
__device__ __forceinline__ void mma_f16(float* c, uint32_t a0, uint32_t a1, uint32_t a2,
                                        uint32_t a3, uint32_t b0, uint32_t b1) {
    asm volatile("mma.sync.aligned.m16n8k16.row.col.f32.f16.f16.f32 "
        "{%0,%1,%2,%3}, {%4,%5,%6,%7}, {%8,%9}, {%0,%1,%2,%3};"
        : "+f"(c[0]), "+f"(c[1]), "+f"(c[2]), "+f"(c[3])
        : "r"(a0), "r"(a1), "r"(a2), "r"(a3), "r"(b0), "r"(b1));
}

// ---------------- fused ln1 + weight conversion ------------------------------
#define D4 262144
#define F4 1048576
#define NCVT ((5*D4 + 2*F4)/256)     /* 13312 */
__global__ void ln1_cvt(const float* __restrict__ x, const float* __restrict__ g,
                        const float* __restrict__ b, __half* __restrict__ out,
                        const float* __restrict__ wq, const float* __restrict__ wk,
                        const float* __restrict__ wv, const float* __restrict__ wo,
                        const float* __restrict__ wd, const float* __restrict__ wff1,
                        const float* __restrict__ wff2, __half* __restrict__ wr)
{
    const int t = threadIdx.x;
    if (blockIdx.x >= TOK) {
        const int i = (blockIdx.x - TOK) * 256 + t;
        const float* src;
        __half2* d2;
        if (i < 3*D4) {
            const int m = i / D4, j = i % D4;
            src = (m == 0) ? wq : (m == 1) ? wk : wv;
            const int row = j >> 8, c4 = j & 255;
            float4 v = ((const float4*)src)[j];
            d2 = (__half2*)(wr + OFF_QKV + (size_t)row*3072 + m*1024 + c4*4);
            d2[0] = __floats2half2_rn(v.x, v.y);
            d2[1] = __floats2half2_rn(v.z, v.w);
            return;
        }
        int j; size_t off;
        if      (i < 4*D4)      { j = i - 3*D4;      src = wo;   off = OFF_WO; }
        else if (i < 5*D4)      { j = i - 4*D4;      src = wd;   off = OFF_WD; }
        else if (i < 5*D4 + F4) { j = i - 5*D4;      src = wff1; off = OFF_WFF1; }
        else                    { j = i - 5*D4 - F4; src = wff2; off = OFF_WFF2; }
        float4 v = ((const float4*)src)[j];
        d2 = (__half2*)(wr + off + (size_t)j*4);
        d2[0] = __floats2half2_rn(v.x, v.y);
        d2[1] = __floats2half2_rn(v.z, v.w);
        return;
    }
    __shared__ float red[16];
    __shared__ float s_mu, s_rstd;
    const int row = blockIdx.x;
    const float4 v = ((const float4*)(x + (size_t)row*DIM))[t];
    float s  = v.x + v.y + v.z + v.w;
    float ss = fmaf(v.x,v.x, fmaf(v.y,v.y, fmaf(v.z,v.z, v.w*v.w)));
    #pragma unroll
    for (int o = 16; o > 0; o >>= 1) {
        s  += __shfl_xor_sync(0xffffffffu, s,  o);
        ss += __shfl_xor_sync(0xffffffffu, ss, o);
    }
    const int w = t >> 5, lane = t & 31;
    if (lane == 0) { red[w] = s; red[8+w] = ss; }
    __syncthreads();
    if (t == 0) {
        float S = 0.f, SS = 0.f;
        #pragma unroll
        for (int i = 0; i < 8; i++) { S += red[i]; SS += red[8+i]; }
        float mu  = S  * (1.0f/DIM);
        float var = SS * (1.0f/DIM) - mu*mu;
        s_mu = mu; s_rstd = rsqrtf(var + 1e-5f);
    }
    __syncthreads();
    const float mu = s_mu, r = s_rstd;
    const float4 gv = ((const float4*)g)[t];
    const float4 bv = ((const float4*)b)[t];
    __half2* o2 = (__half2*)(out + (size_t)row*DIM);
    o2[t*2]   = __floats2half2_rn((v.x-mu)*r*gv.x + bv.x, (v.y-mu)*r*gv.y + bv.y);
    o2[t*2+1] = __floats2half2_rn((v.z-mu)*r*gv.z + bv.z, (v.w-mu)*r*gv.w + bv.w);
}

// ---------------- LayerNorm, fp16 input (for ln2 on x1h) ---------------------
__global__ void ln_h(const __half* __restrict__ x, const float* __restrict__ g,
                     const float* __restrict__ b, __half* __restrict__ out)
{
    __shared__ float red[16];
    __shared__ float s_mu, s_rstd;
    const int row = blockIdx.x, t = threadIdx.x;
    const __half2* x2p = (const __half2*)(x + (size_t)row*DIM);
    const float2 a0 = __half22float2(x2p[t*2]);
    const float2 a1 = __half22float2(x2p[t*2+1]);
    float s  = a0.x + a0.y + a1.x + a1.y;
    float ss = fmaf(a0.x,a0.x, fmaf(a0.y,a0.y, fmaf(a1.x,a1.x, a1.y*a1.y)));
    #pragma unroll
    for (int o = 16; o > 0; o >>= 1) {
        s  += __shfl_xor_sync(0xffffffffu, s,  o);
        ss += __shfl_xor_sync(0xffffffffu, ss, o);
    }
    const int w = t >> 5, lane = t & 31;
    if (lane == 0) { red[w] = s; red[8+w] = ss; }
    __syncthreads();
    if (t == 0) {
        float S = 0.f, SS = 0.f;
        #pragma unroll
        for (int i = 0; i < 8; i++) { S += red[i]; SS += red[8+i]; }
        float mu  = S  * (1.0f/DIM);
        float var = SS * (1.0f/DIM) - mu*mu;
        s_mu = mu; s_rstd = rsqrtf(var + 1e-5f);
    }
    __syncthreads();
    const float mu = s_mu, r = s_rstd;
    const float4 gv = ((const float4*)g)[t];
    const float4 bv = ((const float4*)b)[t];
    __half2* o2 = (__half2*)(out + (size_t)row*DIM);
    o2[t*2]   = __floats2half2_rn((a0.x-mu)*r*gv.x + bv.x, (a0.y-mu)*r*gv.y + bv.y);
    o2[t*2+1] = __floats2half2_rn((a1.x-mu)*r*gv.z + bv.z, (a1.y-mu)*r*gv.w + bv.w);
}

// ---------------- fp16 mma GEMM, 128x128 tiles, 3-stage, 1 bar/iter ----------
// MODE 0: C(fp32) = acc + bias
// MODE 2: C(fp16) = gelu(acc + bias)
// MODE 5: C(fp16) = acc + bias + res(fp16)
// MODE 7: fused qkv: W=[1024][3072]; q -> Cv row-major [TOK][1024];
//         k -> bias cast scatter [b,h,n,dh]; v -> res cast scatter
// MODE 8: W2 batch z=bh: A=ctx+z*DH*DH, W=wo+(z&3)*DH*Ncols,
//         C(fp16) at w2 + (z>>2)*DIM*Ncols + (z&3)*DH*Ncols
// MODE 9: batched over z=b: A=qh+z*SEQ*K, W=w2+z*K*Ncols,
//         res(fp32 x)+z*SEQ*Ncols, C(fp16) + z*SEQ*Ncols
template<int MODE>
__global__ void __launch_bounds__(256, 2)
gemm_mma(const __half* __restrict__ A, const __half* __restrict__ W,
         const float* __restrict__ bias, const float* __restrict__ res,
         void* __restrict__ Cv, int Ncols, int K)
{
    extern __shared__ char dsm[];
    uint32_t aAs[3], aBs[3];
    #pragma unroll
    for (int s = 0; s < 3; s++) {
        aAs[s] = smem_u32(dsm + s*STAGEB);
        aBs[s] = smem_u32(dsm + s*STAGEB + ABYTES);
    }

    size_t cofs = 0;
    if (MODE == 8) {
        const int z = blockIdx.z;
        A += (size_t)z * DH * DH;
        W += (size_t)(z & 3) * DH * Ncols;
        cofs = (size_t)(z >> 2) * DIM * Ncols + (size_t)(z & 3) * DH * Ncols;
    }
    if (MODE == 9) {
        const int z = blockIdx.z;
        A += (size_t)z * SEQ * K;
        W += (size_t)z * K * Ncols;
        res += (size_t)z * SEQ * Ncols;
        cofs = (size_t)z * SEQ * Ncols;
    }

    const int tid  = threadIdx.x;
    const int lane = tid & 31;
    const int w    = tid >> 5;
    const int m0w  = (w >> 2) * 64;
    const int n0w  = (w & 3) * 32;
    const int row0 = blockIdx.y * TM;
    const int col0 = blockIdx.x * TN;
    const int NT   = K / TK;

    const int lr = lane >> 2;
    const int lc = lane & 3;
    const int l15 = lane & 15;
    const int lhi8 = (lane >> 4) * 8;

    auto fill = [&](int buf, int k0) {
        #pragma unroll
        for (int j = 0; j < 4; j++) {
            int f  = tid + 256*j;
            int r  = f >> 3, c8 = f & 7;
            cp16(aAs[buf] + (uint32_t)(r*APITCH + c8*8)*2,
                 A + (size_t)(row0 + r)*K + k0 + c8*8);
        }
        #pragma unroll
        for (int j = 0; j < 4; j++) {
            int f  = tid + 256*j;
            int kr = f >> 4, c8 = f & 15;
            cp16(aBs[buf] + (uint32_t)(kr*BPITCH + c8*8)*2,
                 W + (size_t)(k0 + kr)*Ncols + col0 + c8*8);
        }
        asm volatile("cp.async.commit_group;");
    };

    float acc[4][4][4];
    #pragma unroll
    for (int i = 0; i < 4; i++)
        #pragma unroll
        for (int j = 0; j < 4; j++)
            #pragma unroll
            for (int r = 0; r < 4; r++) acc[i][j][r] = 0.f;

    fill(0, 0);
    fill(1, TK);

    int buf = 0;
    for (int t = 0; t < NT; t++) {
        if (t + 1 < NT) asm volatile("cp.async.wait_group 1;");
        else            asm volatile("cp.async.wait_group 0;");
        __syncthreads();
        if (t + 2 < NT) fill((t + 2) % 3, (t + 2) * TK);

        const uint32_t a_lm = aAs[buf] + (uint32_t)((m0w + l15)*APITCH + lhi8)*2;
        const uint32_t b_lm = aBs[buf] + (uint32_t)(l15*BPITCH + n0w + lhi8)*2;

        #pragma unroll
        for (int kk = 0; kk < 4; kk++) {
            uint32_t af[4][4];
            #pragma unroll
            for (int mf = 0; mf < 4; mf++)
                ldm_x4(af[mf], a_lm + (uint32_t)(mf*16*APITCH + kk*16)*2);

            uint32_t bf[2][4];
            #pragma unroll
            for (int np = 0; np < 2; np++)
                ldm_x4_t(bf[np], b_lm + (uint32_t)(kk*16*BPITCH + np*16)*2);

            #pragma unroll
            for (int mf = 0; mf < 4; mf++)
                #pragma unroll
                for (int nf = 0; nf < 4; nf++)
                    mma_f16(acc[mf][nf],
                            af[mf][0], af[mf][1], af[mf][2], af[mf][3],
                            bf[nf >> 1][(nf & 1)*2], bf[nf >> 1][(nf & 1)*2 + 1]);
        }
        buf = (buf + 1 == 3) ? 0 : buf + 1;
    }

    // ---- epilogue ----
    float*  Cf = (float*)Cv;
    __half* Ch = (__half*)Cv;
    #pragma unroll
    for (int mf = 0; mf < 4; mf++) {
        #pragma unroll
        for (int half_ = 0; half_ < 2; half_++) {
            const int grow = row0 + m0w + mf*16 + lr + half_*8;
            #pragma unroll
            for (int nf = 0; nf < 4; nf++) {
                const int gcol = col0 + n0w + nf*8 + 2*lc;
                float v0 = acc[mf][nf][half_*2 + 0];
                float v1 = acc[mf][nf][half_*2 + 1];
                if (MODE == 7) {
                    const int mat  = gcol >> 10;
                    const int hcol = gcol & 1023;
                    if (mat == 0) {
                        *(__half2*)(Ch + (size_t)grow*DIM + hcol) = __floats2half2_rn(v0, v1);
                    } else {
                        const int head = hcol >> 8;
                        const int dh0  = hcol & 255;
                        const int b_   = grow >> 12;
                        const int n_   = grow & 4095;
                        const size_t off = ((size_t)((b_*NH + head)*SEQ + n_))*DH + dh0;
                        __half* dst = (mat == 1) ? (__half*)bias : (__half*)res;
                        *(__half2*)(dst + off) = __floats2half2_rn(v0, v1);
                    }
                } else if (MODE == 8) {
                    *(__half2*)(Ch + cofs + (size_t)grow*Ncols + gcol) = __floats2half2_rn(v0, v1);
                } else {
                    v0 += bias[gcol];
                    v1 += bias[gcol + 1];
                    if (MODE == 2) { v0 = gelu_tanh(v0); v1 = gelu_tanh(v1); }
                    if (MODE == 5) {
                        const __half2 rv = *(const __half2*)((const __half*)res +
                                           (size_t)grow*Ncols + gcol);
                        const float2 rf = __half22float2(rv);
                        v0 += rf.x; v1 += rf.y;
                    }
                    if (MODE == 9) {
                        const float2 rv = *(const float2*)(res + (size_t)grow*Ncols + gcol);
                        v0 += rv.x; v1 += rv.y;
                    }
                    if (MODE == 2 || MODE == 5 || MODE == 9) {
                        *(__half2*)(Ch + cofs + (size_t)grow*Ncols + gcol) =
                            __floats2half2_rn(v0, v1);
                    } else {
                        *(float2*)(Cf + cofs + (size_t)grow*Ncols + gcol) = make_float2(v0, v1);
                    }
                }
            }
        }
    }
}

// ---------------- ctx = k^T @ v (fp16 mma, both operands transposed) --------
__global__ void __launch_bounds__(128, 2)
ctx_mma(const __half* __restrict__ kh, const __half* __restrict__ vh,
        __half* __restrict__ ctx)
{
    __shared__ __half Ks[2][CTK][CPITCH];
    __shared__ __half Vs[2][CTK][CPITCH];
    const int bh = blockIdx.z;
    const int d0 = blockIdx.y * 64, e0 = blockIdx.x * 64;
    const __half* kb = kh + (size_t)bh*SEQ*DH;
    const __half* vb = vh + (size_t)bh*SEQ*DH;
    const int tid = threadIdx.x, lane = tid & 31, w = tid >> 5;
    const int m0w = (w >> 1) * 32, n0w = (w & 1) * 32;

    const uint32_t kbase[2] = { smem_u32(&Ks[0][0][0]), smem_u32(&Ks[1][0][0]) };
    const uint32_t vbase[2] = { smem_u32(&Vs[0][0][0]), smem_u32(&Vs[1][0][0]) };

    auto fill = [&](int buf, int n0) {
        #pragma unroll
        for (int j = 0; j < 4; j++) {
            int f = tid + 128*j;
            int r = f >> 3, c8 = f & 7;
            cp16(kbase[buf] + (uint32_t)(r*CPITCH + c8*8)*2, kb + (size_t)(n0+r)*DH + d0 + c8*8);
            cp16(vbase[buf] + (uint32_t)(r*CPITCH + c8*8)*2, vb + (size_t)(n0+r)*DH + e0 + c8*8);
        }
        asm volatile("cp.async.commit_group;");
    };

    float acc[2][4][4];
    #pragma unroll
    for (int i = 0; i < 2; i++)
        #pragma unroll
        for (int j = 0; j < 4; j++)
            #pragma unroll
            for (int r = 0; r < 4; r++) acc[i][j][r] = 0.f;

    const int arow = (lane & 7) + ((lane >> 4) << 3);
    const int acol = ((lane >> 3) & 1) * 8;
    const int l15 = lane & 15, lhi8 = (lane >> 4) * 8;
    const int lr = lane >> 2, lc = lane & 3;

    fill(0, 0);
    const int NTc = SEQ / CTK;
    for (int t = 0; t < NTc; t++) {
        if (t + 1 < NTc) {
            fill((t + 1) & 1, (t + 1) * CTK);
            asm volatile("cp.async.wait_group 1;");
        } else {
            asm volatile("cp.async.wait_group 0;");
        }
        __syncthreads();
        const uint32_t ka = kbase[t & 1];
        const uint32_t va = vbase[t & 1];

        #pragma unroll
        for (int kk = 0; kk < 4; kk++) {
            uint32_t af[2][4];
            #pragma unroll
            for (int mf = 0; mf < 2; mf++)
                ldm_x4_t(af[mf], ka + (uint32_t)((kk*16 + arow)*CPITCH + m0w + mf*16 + acol)*2);
            uint32_t bf[2][4];
            #pragma unroll
            for (int np = 0; np < 2; np++)
                ldm_x4_t(bf[np], va + (uint32_t)((kk*16 + l15)*CPITCH + n0w + np*16 + lhi8)*2);
            #pragma unroll
            for (int mf = 0; mf < 2; mf++)
                #pragma unroll
                for (int nf = 0; nf < 4; nf++)
                    mma_f16(acc[mf][nf],
                            af[mf][0], af[mf][1], af[mf][2], af[mf][3],
                            bf[nf >> 1][(nf & 1)*2], bf[nf >> 1][(nf & 1)*2 + 1]);
        }
        __syncthreads();
    }

    __half* cb = ctx + (size_t)bh*DH*DH;
    #pragma unroll
    for (int mf = 0; mf < 2; mf++)
        #pragma unroll
        for (int half_ = 0; half_ < 2; half_++) {
            const int grow = d0 + m0w + mf*16 + lr + half_*8;
            #pragma unroll
            for (int nf = 0; nf < 4; nf++) {
                const int gcol = e0 + n0w + nf*8 + 2*lc;
                *(__half2*)(cb + (size_t)grow*DH + gcol) =
                    __floats2half2_rn(acc[mf][nf][half_*2], acc[mf][nf][half_*2 + 1]);
            }
        }
}

// ---------------- fused q softmax + k softmax partial ------------------------
__global__ void qsm_ksmp(__half* __restrict__ q, const __half* __restrict__ k,
                         float* __restrict__ part)
{
    if (blockIdx.x >= 8192) {
        const int idx = blockIdx.x - 8192;
        const int ch = idx & 15, bh = idx >> 4, t = threadIdx.x;
        const __half* kp = k + ((size_t)bh*SEQ + (size_t)ch*CHUNK)*DH + t;
        float m = -INFINITY, s = 0.f;
        for (int i = 0; i < CHUNK; i++) {
            const float vv = __half2float(kp[(size_t)i*DH]) * 0.25f;
            const float nm = fmaxf(m, vv);
            s = s*expf(m - nm) + expf(vv - nm);
            m = nm;
        }
        float* pp = part + (size_t)((bh*KCH + ch)*2)*DH;
        pp[t] = m; pp[DH + t] = s;
        return;
    }
    const int warp = (blockIdx.x * blockDim.x + threadIdx.x) >> 5;
    const int lane = threadIdx.x & 31;
    __half* row = q + (size_t)warp * DH;
    float v[8];
    float m = -INFINITY;
    #pragma unroll
    for (int j = 0; j < 8; j++) {
        v[j] = __half2float(row[j*32 + lane]) * 0.25f;
        m = fmaxf(m, v[j]);
    }
    #pragma unroll
    for (int o = 16; o > 0; o >>= 1) m = fmaxf(m, __shfl_xor_sync(0xffffffffu, m, o));
    float s = 0.f;
    #pragma unroll
    for (int j = 0; j < 8; j++) { v[j] = expf(v[j] - m); s += v[j]; }
    #pragma unroll
    for (int o = 16; o > 0; o >>= 1) s += __shfl_xor_sync(0xffffffffu, s, o);
    const float inv = 1.0f / s;
    #pragma unroll
    for (int j = 0; j < 8; j++) row[j*32 + lane] = __float2half_rn(v[j] * inv);
}

// ---------------- k softmax normalize, 4x parallel over quarter-chunks ------
__global__ void ksm_norm(__half* __restrict__ k, const float* __restrict__ part)
{
    const int bh = blockIdx.y;
    const int ch = blockIdx.x >> 2;
    const int qu = blockIdx.x & 3;
    const int t  = threadIdx.x;
    float M = -INFINITY;
    #pragma unroll
    for (int c = 0; c < KCH; c++)
        M = fmaxf(M, part[(size_t)((bh*KCH + c)*2)*DH + t]);
    float S = 0.f;
    #pragma unroll
    for (int c = 0; c < KCH; c++) {
        const float* pp = part + (size_t)((bh*KCH + c)*2)*DH;
        S += pp[DH + t] * expf(pp[t] - M);
    }
    const float inv = 1.0f / S;
    __half* kp = k + ((size_t)bh*SEQ + (size_t)ch*CHUNK + (size_t)qu*(CHUNK/4))*DH + t;
    #pragma unroll 4
    for (int i = 0; i < CHUNK/4; i++) {
        const float vv = __half2float(kp[(size_t)i*DH]) * 0.25f;
        kp[(size_t)i*DH] = __float2half_rn(expf(vv - M) * inv);
    }
}

// ---------------- launch ----------------------------------------------------
extern "C" void kernel_launch(void* const* d_in, const int* in_sizes, int n_in,
                              void* d_out, int out_size)
{
    const float* x    = (const float*)d_in[0];
    const float* ln1g = (const float*)d_in[1];
    const float* ln1b = (const float*)d_in[2];
    const float* wq   = (const float*)d_in[3];
    const float* wk   = (const float*)d_in[4];
    const float* wv   = (const float*)d_in[5];
    const float* wo   = (const float*)d_in[6];
    const float* bo   = (const float*)d_in[7];
    const float* ln2g = (const float*)d_in[8];
    const float* ln2b = (const float*)d_in[9];
    const float* wff1 = (const float*)d_in[10];
    const float* bff1 = (const float*)d_in[11];
    const float* wff2 = (const float*)d_in[12];
    const float* bff2 = (const float*)d_in[13];
    const float* wd   = (const float*)d_in[14];
    const float* bd   = (const float*)d_in[15];
    float* out = (float*)d_out;

    float *part;
    __half *x1h,*h,*qh,*kh,*vh,*ctxh,*w2h,*ffh,*x2h,*wr;
    cudaGetSymbolAddress((void**)&part, g_part);
    cudaGetSymbolAddress((void**)&x1h,  g_x1h);
    cudaGetSymbolAddress((void**)&h,    g_h);
    cudaGetSymbolAddress((void**)&qh,   g_qh);
    cudaGetSymbolAddress((void**)&kh,   g_kh);
    cudaGetSymbolAddress((void**)&vh,   g_vh);
    cudaGetSymbolAddress((void**)&ctxh, g_ctxh);
    cudaGetSymbolAddress((void**)&w2h,  g_w2h);
    cudaGetSymbolAddress((void**)&ffh,  g_ffh);
    cudaGetSymbolAddress((void**)&x2h,  g_x2h);
    cudaGetSymbolAddress((void**)&wr,   g_wr);

    cudaFuncSetAttribute(gemm_mma<0>, cudaFuncAttributeMaxDynamicSharedMemorySize, SMEM3);
    cudaFuncSetAttribute(gemm_mma<2>, cudaFuncAttributeMaxDynamicSharedMemorySize, SMEM3);
    cudaFuncSetAttribute(gemm_mma<5>, cudaFuncAttributeMaxDynamicSharedMemorySize, SMEM3);
    cudaFuncSetAttribute(gemm_mma<7>, cudaFuncAttributeMaxDynamicSharedMemorySize, SMEM3);
    cudaFuncSetAttribute(gemm_mma<8>, cudaFuncAttributeMaxDynamicSharedMemorySize, SMEM3);
    cudaFuncSetAttribute(gemm_mma<9>, cudaFuncAttributeMaxDynamicSharedMemorySize, SMEM3);

    // --- attention block (ln1 runs concurrently with weight conversion) ---
    ln1_cvt<<<TOK + NCVT, 256>>>(x, ln1g, ln1b, h,
                                 wq, wk, wv, wo, wd, wff1, wff2, wr);
    gemm_mma<7><<<dim3(24, 128), 256, SMEM3>>>(h, wr + OFF_QKV,
                                               (const float*)kh, (const float*)vh,
                                               qh, 3*DIM, DIM);
    qsm_ksmp<<<8192 + 256, 256>>>(qh, kh, part);
    ksm_norm<<<dim3(KCH*4, NBH), 256>>>(kh, part);
    ctx_mma <<<dim3(4, 4, NBH), 128>>>(kh, vh, ctxh);
    gemm_mma<8><<<dim3(8, 2, NBH), 256, SMEM3>>>(ctxh, wr + OFF_WO, nullptr, nullptr,
                                                 w2h, DIM, DH);
    /* x1h(fp16) = q @ W2 + bo + x(fp32) */
    gemm_mma<9><<<dim3(8, 32, BATCH), 256, SMEM3>>>(qh, w2h, bo, x, x1h, DIM, DIM);

    // --- FFN block (fp16 residual stream) ---
    ln_h<<<TOK, 256>>>(x1h, ln2g, ln2b, h);
    gemm_mma<2><<<dim3(32, 128), 256, SMEM3>>>(h, wr + OFF_WFF1, bff1, nullptr, ffh, FFD, DIM);
    gemm_mma<5><<<dim3(8, 128), 256, SMEM3>>>(ffh, wr + OFF_WFF2, bff2,
                                              (const float*)x1h, x2h, DIM, FFD);

    // --- trailing dense ---
    gemm_mma<0><<<dim3(8, 128), 256, SMEM3>>>(x2h, wr + OFF_WD, bd, nullptr, out, DIM, DIM);
}